// round 3
// baseline (speedup 1.0000x reference)
#include <cuda_runtime.h>
#include <math.h>

// Problem constants
#define BB 4
#define TT 2048
#define CC 1024
#define HH 16
#define DHD 64
#define MM (BB*TT)          // 8192 rows

// Scratch (allocation-free rule: __device__ globals)
__device__ float g_Q[BB*HH*TT*DHD];   // [B,H,T,Dh]
__device__ float g_K[BB*HH*TT*DHD];
__device__ float g_V[BB*HH*TT*DHD];
__device__ float g_O[MM*CC];          // attention output, [B,T,C]

// ---------------------------------------------------------------------------
// SGEMM: C[M,N] = A[M,1024] @ B[1024,N] + bias
// 128x128 block tile, BK=8, 8x8 per-thread micro tile, 256 threads.
// MODE 0: plain store to O0[M,N].
// MODE 1: QKV scatter -> O0/O1/O2 as [B,H,T,Dh].
// ---------------------------------------------------------------------------
template<int N, int MODE>
__global__ __launch_bounds__(256, 2)
void sgemm_k(const float* __restrict__ A, const float* __restrict__ Bw,
             const float* __restrict__ bias,
             float* __restrict__ O0, float* __restrict__ O1, float* __restrict__ O2)
{
    __shared__ float As[8*128];   // [k][m]
    __shared__ float Bs[8*128];   // [k][n]

    const int bm = blockIdx.y * 128;
    const int bn = blockIdx.x * 128;
    const int tid = threadIdx.x;
    const int tr = (tid >> 4) << 3;   // 0..120 step 8
    const int tc = (tid & 15) << 3;

    const int arow = tid >> 1;            // 0..127
    const int acg  = (tid & 1) << 2;      // 0 or 4
    const int brow = tid >> 5;            // 0..7
    const int bcol = (tid & 31) << 2;     // 0..124 step 4

    float acc[8][8];
#pragma unroll
    for (int i = 0; i < 8; i++)
#pragma unroll
        for (int j = 0; j < 8; j++) acc[i][j] = 0.f;

    for (int k0 = 0; k0 < 1024; k0 += 8) {
        float4 av = *(const float4*)&A[(size_t)(bm + arow) * 1024 + k0 + acg];
        As[(acg+0)*128 + arow] = av.x;
        As[(acg+1)*128 + arow] = av.y;
        As[(acg+2)*128 + arow] = av.z;
        As[(acg+3)*128 + arow] = av.w;
        *(float4*)&Bs[brow*128 + bcol] =
            *(const float4*)&Bw[(size_t)(k0 + brow) * N + bn + bcol];
        __syncthreads();

#pragma unroll
        for (int kk = 0; kk < 8; kk++) {
            float4 a0 = *(const float4*)&As[kk*128 + tr];
            float4 a1 = *(const float4*)&As[kk*128 + tr + 4];
            float4 b0 = *(const float4*)&Bs[kk*128 + tc];
            float4 b1 = *(const float4*)&Bs[kk*128 + tc + 4];
            float ar[8] = {a0.x,a0.y,a0.z,a0.w,a1.x,a1.y,a1.z,a1.w};
            float br[8] = {b0.x,b0.y,b0.z,b0.w,b1.x,b1.y,b1.z,b1.w};
#pragma unroll
            for (int i = 0; i < 8; i++)
#pragma unroll
                for (int j = 0; j < 8; j++)
                    acc[i][j] += ar[i] * br[j];
        }
        __syncthreads();
    }

#pragma unroll
    for (int i = 0; i < 8; i++) {
        const int m = bm + tr + i;
#pragma unroll
        for (int j = 0; j < 8; j++) {
            const int n = bn + tc + j;
            float v = acc[i][j] + bias[n];
            if (MODE == 0) {
                O0[(size_t)m * N + n] = v;
            } else {
                const int sec = n >> 10;           // 0=q,1=k,2=v
                const int c   = n & 1023;
                const int h   = c >> 6;
                const int d   = c & 63;
                const int b   = m >> 11;
                const int t   = m & 2047;
                float* dst = (sec == 0) ? O0 : ((sec == 1) ? O1 : O2);
                dst[(((size_t)(b*HH + h))*TT + t)*DHD + d] = v;
            }
        }
    }
}

// ---------------------------------------------------------------------------
// Causal flash attention, fp32.
// Block: 64 queries of one (b,h). 256 threads: row r = tid/4, lane-in-row cq = tid%4.
// Thread owns columns {cq, cq+4, ..., cq+60} (16) of the 64-wide S/P/O tiles.
// Smem stride 65 => conflict-free broadcast reads for both S and PV inner loops.
// ---------------------------------------------------------------------------
#define ATT_STRIDE 65
#define ATT_SMEM_FLOATS (4*64*ATT_STRIDE)
#define ATT_SMEM_BYTES  (ATT_SMEM_FLOATS*4)

__global__ __launch_bounds__(256, 2)
void attn_k(float* __restrict__ O)
{
    extern __shared__ float sm[];
    float* Qs = sm;                       // [64][65]  (pre-scaled by 1/8)
    float* Ks = sm + 64*ATT_STRIDE;       // [64 keys][65]
    float* Vs = sm + 2*64*ATT_STRIDE;     // [64 keys][65]
    float* Ps = sm + 3*64*ATT_STRIDE;     // [64 rows][65]

    const int tid = threadIdx.x;
    const int bh  = blockIdx.y;           // 0..63
    const int qt  = blockIdx.x;           // 0..31
    const int b   = bh >> 4;
    const int h   = bh & 15;
    const size_t base = (size_t)bh * TT * DHD;
    const int q0 = qt * 64;

    // Load Q tile, pre-scaled by 1/sqrt(Dh)=0.125
#pragma unroll
    for (int it = 0; it < 4; it++) {
        int idx = it*256 + tid;           // float4 index, 1024 total
        int row = idx >> 4;
        int c4  = (idx & 15) << 2;
        float4 v = *(const float4*)&g_Q[base + (size_t)(q0 + row)*DHD + c4];
        Qs[row*ATT_STRIDE + c4 + 0] = v.x * 0.125f;
        Qs[row*ATT_STRIDE + c4 + 1] = v.y * 0.125f;
        Qs[row*ATT_STRIDE + c4 + 2] = v.z * 0.125f;
        Qs[row*ATT_STRIDE + c4 + 3] = v.w * 0.125f;
    }

    const int r  = tid >> 2;
    const int cq = tid & 3;

    float mrow = -INFINITY, lrow = 0.f;
    float o[16];
#pragma unroll
    for (int i = 0; i < 16; i++) o[i] = 0.f;

    __syncthreads();

    for (int kt = 0; kt <= qt; kt++) {
        const int k0 = kt * 64;
        // Load K and V tiles
#pragma unroll
        for (int it = 0; it < 4; it++) {
            int idx = it*256 + tid;
            int row = idx >> 4;
            int c4  = (idx & 15) << 2;
            float4 kv = *(const float4*)&g_K[base + (size_t)(k0 + row)*DHD + c4];
            Ks[row*ATT_STRIDE + c4 + 0] = kv.x;
            Ks[row*ATT_STRIDE + c4 + 1] = kv.y;
            Ks[row*ATT_STRIDE + c4 + 2] = kv.z;
            Ks[row*ATT_STRIDE + c4 + 3] = kv.w;
            float4 vv = *(const float4*)&g_V[base + (size_t)(k0 + row)*DHD + c4];
            Vs[row*ATT_STRIDE + c4 + 0] = vv.x;
            Vs[row*ATT_STRIDE + c4 + 1] = vv.y;
            Vs[row*ATT_STRIDE + c4 + 2] = vv.z;
            Vs[row*ATT_STRIDE + c4 + 3] = vv.w;
        }
        __syncthreads();

        // S = Q K^T (scaled)
        float s[16];
#pragma unroll
        for (int i = 0; i < 16; i++) s[i] = 0.f;
        const float* qrow = Qs + r*ATT_STRIDE;
        const float* kbase = Ks + cq*ATT_STRIDE;
#pragma unroll 8
        for (int d = 0; d < 64; d++) {
            float qd = qrow[d];
#pragma unroll
            for (int i = 0; i < 16; i++)
                s[i] += qd * kbase[i*4*ATT_STRIDE + d];
        }

        if (kt == qt) {
#pragma unroll
            for (int i = 0; i < 16; i++)
                if (cq + 4*i > r) s[i] = -INFINITY;
        }

        // Row max across this thread's 16 cols, then across 4 lanes of the row
        float mt = s[0];
#pragma unroll
        for (int i = 1; i < 16; i++) mt = fmaxf(mt, s[i]);
        mt = fmaxf(mt, __shfl_xor_sync(0xffffffffu, mt, 1));
        mt = fmaxf(mt, __shfl_xor_sync(0xffffffffu, mt, 2));

        float mnew = fmaxf(mrow, mt);
        float corr = __expf(mrow - mnew);
        float p[16];
        float ls = 0.f;
#pragma unroll
        for (int i = 0; i < 16; i++) { p[i] = __expf(s[i] - mnew); ls += p[i]; }
        ls += __shfl_xor_sync(0xffffffffu, ls, 1);
        ls += __shfl_xor_sync(0xffffffffu, ls, 2);

        lrow = lrow * corr + ls;
        mrow = mnew;
#pragma unroll
        for (int i = 0; i < 16; i++) o[i] *= corr;

        // Publish P row to smem
#pragma unroll
        for (int i = 0; i < 16; i++)
            Ps[r*ATT_STRIDE + cq + 4*i] = p[i];
        __syncthreads();

        // O += P @ V
        const float* prow  = Ps + r*ATT_STRIDE;
        const float* vbase = Vs + cq;
#pragma unroll 8
        for (int j = 0; j < 64; j++) {
            float pj = prow[j];
#pragma unroll
            for (int i = 0; i < 16; i++)
                o[i] += pj * vbase[j*ATT_STRIDE + 4*i];
        }
        __syncthreads();   // protect Ks/Vs/Ps before next iteration's loads
    }

    const float inv = 1.0f / lrow;
    const size_t ob = ((size_t)b*TT + q0 + r) * CC + h*DHD + cq;
#pragma unroll
    for (int i = 0; i < 16; i++)
        O[ob + 4*i] = o[i] * inv;
}

// ---------------------------------------------------------------------------
extern "C" void kernel_launch(void* const* d_in, const int* in_sizes, int n_in,
                              void* d_out, int out_size)
{
    const float* x     = (const float*)d_in[0];   // [4,2048,1024]
    const float* W_qkv = (const float*)d_in[1];   // [1024,3072]
    const float* b_qkv = (const float*)d_in[2];   // [3072]
    const float* W_out = (const float*)d_in[3];   // [1024,1024]
    const float* b_out = (const float*)d_in[4];   // [1024]
    float* out = (float*)d_out;                   // [4,2048,1024]

    void *pQ, *pK, *pV, *pO;
    cudaGetSymbolAddress(&pQ, g_Q);
    cudaGetSymbolAddress(&pK, g_K);
    cudaGetSymbolAddress(&pV, g_V);
    cudaGetSymbolAddress(&pO, g_O);

    cudaFuncSetAttribute(attn_k, cudaFuncAttributeMaxDynamicSharedMemorySize,
                         ATT_SMEM_BYTES);

    // 1) QKV projection + scatter to [B,H,T,Dh]
    {
        dim3 grid(3072/128, MM/128);
        sgemm_k<3072,1><<<grid, 256>>>(x, W_qkv, b_qkv,
                                       (float*)pQ, (float*)pK, (float*)pV);
    }
    // 2) Causal flash attention -> g_O [B,T,C]
    {
        dim3 grid(TT/64, BB*HH);
        attn_k<<<grid, 256, ATT_SMEM_BYTES>>>((float*)pO);
    }
    // 3) Output projection -> d_out
    {
        dim3 grid(1024/128, MM/128);
        sgemm_k<1024,0><<<grid, 256>>>((const float*)pO, W_out, b_out,
                                       out, nullptr, nullptr);
    }
}

// round 4
// speedup vs baseline: 2.7551x; 2.7551x over previous
#include <cuda_runtime.h>
#include <math.h>

// Problem constants
#define BB 4
#define TT 2048
#define CC 1024
#define HH 16
#define DHD 64
#define MM (BB*TT)          // 8192 rows

// Scratch (allocation-free rule: __device__ globals)
__device__ float g_Q[BB*HH*TT*DHD];   // [B,H,T,Dh]
__device__ float g_K[BB*HH*TT*DHD];
__device__ float g_V[BB*HH*TT*DHD];
__device__ float g_O[MM*CC];          // attention output, [B,T,C]

// ---------------------------------------------------------------------------
// tf32 helpers
// ---------------------------------------------------------------------------
__device__ __forceinline__ unsigned f2tf(float x) {
    unsigned r;
    asm("cvt.rna.tf32.f32 %0, %1;" : "=r"(r) : "f"(x));
    return r;
}

__device__ __forceinline__ void mma_tf32(float c[4], const unsigned a[4],
                                         const unsigned b[2]) {
    asm volatile(
        "mma.sync.aligned.m16n8k8.row.col.f32.tf32.tf32.f32 "
        "{%0,%1,%2,%3},{%4,%5,%6,%7},{%8,%9},{%0,%1,%2,%3};"
        : "+f"(c[0]), "+f"(c[1]), "+f"(c[2]), "+f"(c[3])
        : "r"(a[0]), "r"(a[1]), "r"(a[2]), "r"(a[3]), "r"(b[0]), "r"(b[1]));
}

// ---------------------------------------------------------------------------
// tf32 tensor-core GEMM: C[M,N] = A[M,1024] @ B[1024,N] + bias
// 128x128 block tile, BK=32. 8 warps (2 M x 4 N), warp tile 64x32.
// Fragment LDS strides: As stride 36 (==4 mod 32, banks 4g+t unique),
//                       Bs stride 136 (==8 mod 32, banks 8t+g unique).
// MODE 0: plain store.  MODE 1: QKV scatter to [B,H,T,Dh].
// ---------------------------------------------------------------------------
#define AS_STRIDE 36
#define BS_STRIDE 136

template<int N, int MODE>
__global__ __launch_bounds__(256)
void sgemm_tc(const float* __restrict__ A, const float* __restrict__ Bw,
              const float* __restrict__ bias,
              float* __restrict__ O0, float* __restrict__ O1, float* __restrict__ O2)
{
    __shared__ unsigned As[128 * AS_STRIDE];   // A(m,k) at m*36+k
    __shared__ unsigned Bs[32 * BS_STRIDE];    // B(k,n) at k*136+n

    const int bm = blockIdx.y * 128;
    const int bn = blockIdx.x * 128;
    const int tid  = threadIdx.x;
    const int w    = tid >> 5;
    const int lane = tid & 31;
    const int g    = lane >> 2;        // groupID
    const int t    = lane & 3;         // threadID in group
    const int wm   = (w >> 2) * 64;    // warp M offset (0 or 64)
    const int wn   = (w & 3) * 32;     // warp N offset

    float acc[4][4][4];
#pragma unroll
    for (int mi = 0; mi < 4; mi++)
#pragma unroll
        for (int ni = 0; ni < 4; ni++)
#pragma unroll
            for (int c = 0; c < 4; c++) acc[mi][ni][c] = 0.f;

    float4 Ag[4], Bg[4];
    // prologue: load k0 = 0
#pragma unroll
    for (int it = 0; it < 4; it++) {
        int i = tid + it * 256;
        Ag[it] = *(const float4*)&A[(size_t)(bm + (i >> 3)) * 1024 + ((i & 7) << 2)];
        Bg[it] = *(const float4*)&Bw[(size_t)(i >> 5) * N + bn + ((i & 31) << 2)];
    }

    for (int k0 = 0; k0 < 1024; k0 += 32) {
        __syncthreads();
        // store prefetched tile to smem (cvt to tf32)
#pragma unroll
        for (int it = 0; it < 4; it++) {
            int i = tid + it * 256;
            uint4 pa = { f2tf(Ag[it].x), f2tf(Ag[it].y), f2tf(Ag[it].z), f2tf(Ag[it].w) };
            *(uint4*)&As[(i >> 3) * AS_STRIDE + ((i & 7) << 2)] = pa;
            uint4 pb = { f2tf(Bg[it].x), f2tf(Bg[it].y), f2tf(Bg[it].z), f2tf(Bg[it].w) };
            *(uint4*)&Bs[(i >> 5) * BS_STRIDE + ((i & 31) << 2)] = pb;
        }
        __syncthreads();

        // prefetch next K-slab
        if (k0 + 32 < 1024) {
#pragma unroll
            for (int it = 0; it < 4; it++) {
                int i = tid + it * 256;
                Ag[it] = *(const float4*)&A[(size_t)(bm + (i >> 3)) * 1024 + k0 + 32 + ((i & 7) << 2)];
                Bg[it] = *(const float4*)&Bw[(size_t)(k0 + 32 + (i >> 5)) * N + bn + ((i & 31) << 2)];
            }
        }

        // compute on current slab
#pragma unroll
        for (int kk = 0; kk < 4; kk++) {
            unsigned a[4][4];
#pragma unroll
            for (int mi = 0; mi < 4; mi++) {
                int rm = wm + mi * 16;
                a[mi][0] = As[(rm + g)     * AS_STRIDE + kk * 8 + t];
                a[mi][1] = As[(rm + g + 8) * AS_STRIDE + kk * 8 + t];
                a[mi][2] = As[(rm + g)     * AS_STRIDE + kk * 8 + t + 4];
                a[mi][3] = As[(rm + g + 8) * AS_STRIDE + kk * 8 + t + 4];
            }
#pragma unroll
            for (int ni = 0; ni < 4; ni++) {
                int nb = wn + ni * 8;
                unsigned b[2];
                b[0] = Bs[(kk * 8 + t)     * BS_STRIDE + nb + g];
                b[1] = Bs[(kk * 8 + t + 4) * BS_STRIDE + nb + g];
#pragma unroll
                for (int mi = 0; mi < 4; mi++)
                    mma_tf32(acc[mi][ni], a[mi], b);
            }
        }
    }

    // epilogue
#pragma unroll
    for (int mi = 0; mi < 4; mi++) {
#pragma unroll
        for (int ni = 0; ni < 4; ni++) {
            int r0 = bm + wm + mi * 16 + g;
            int c0 = bn + wn + ni * 8 + 2 * t;
            float b0 = bias[c0], b1 = bias[c0 + 1];
            float v00 = acc[mi][ni][0] + b0, v01 = acc[mi][ni][1] + b1;
            float v10 = acc[mi][ni][2] + b0, v11 = acc[mi][ni][3] + b1;
            if (MODE == 0) {
                *(float2*)&O0[(size_t)r0 * N + c0]       = make_float2(v00, v01);
                *(float2*)&O0[(size_t)(r0 + 8) * N + c0] = make_float2(v10, v11);
            } else {
#pragma unroll
                for (int e = 0; e < 4; e++) {
                    int m = r0 + ((e >> 1) ? 8 : 0);
                    int n = c0 + (e & 1);
                    float v = (e == 0) ? v00 : (e == 1) ? v01 : (e == 2) ? v10 : v11;
                    const int sec = n >> 10;
                    const int cc  = n & 1023;
                    const int h   = cc >> 6;
                    const int d   = cc & 63;
                    const int b   = m >> 11;
                    const int tt  = m & 2047;
                    float* dst = (sec == 0) ? O0 : ((sec == 1) ? O1 : O2);
                    dst[(((size_t)(b * HH + h)) * TT + tt) * DHD + d] = v;
                }
            }
        }
    }
}

// ---------------------------------------------------------------------------
// Causal flash attention with tf32 tensor cores.
// Block = 64 queries of one (b,h). 128 threads = 4 warps, warp w owns
// query rows [16w, 16w+16) -> softmax rows stay inside the warp.
// S = Q K^T : A=Qs (stride 68), B from Ks (stride 68, banks 4g+t).
// O += P V  : A=Ps (stride 68), B from Vs (stride 72, banks 8t+g).
// ---------------------------------------------------------------------------
#define QS_STRIDE 68
#define VS_STRIDE 72
#define ATT_SMEM_U32 (3*64*QS_STRIDE + 64*VS_STRIDE)
#define ATT_SMEM_BYTES (ATT_SMEM_U32*4)

__global__ __launch_bounds__(128)
void attn_tc(float* __restrict__ O)
{
    extern __shared__ unsigned sm[];
    unsigned* Qs = sm;                                  // [64][68]
    unsigned* Ks = sm + 64 * QS_STRIDE;                 // [64][68]
    unsigned* Ps = sm + 2 * 64 * QS_STRIDE;             // [64][68]
    unsigned* Vs = sm + 3 * 64 * QS_STRIDE;             // [64][72]

    const int tid  = threadIdx.x;
    const int w    = tid >> 5;
    const int lane = tid & 31;
    const int g    = lane >> 2;
    const int t    = lane & 3;
    const int bh   = blockIdx.y;            // 0..63
    const int qt   = blockIdx.x;            // 0..31
    const int b    = bh >> 4;
    const int h    = bh & 15;
    const size_t base = (size_t)bh * TT * DHD;
    const int q0   = qt * 64;
    const int rw   = w * 16;                // warp row base in tile

    // Load Q tile, pre-scaled by 1/sqrt(64)=0.125, cvt to tf32
#pragma unroll
    for (int it = 0; it < 8; it++) {
        int i   = tid + it * 128;
        int row = i >> 4;
        int c4  = (i & 15) << 2;
        float4 v = *(const float4*)&g_Q[base + (size_t)(q0 + row) * DHD + c4];
        uint4 u = { f2tf(v.x * 0.125f), f2tf(v.y * 0.125f),
                    f2tf(v.z * 0.125f), f2tf(v.w * 0.125f) };
        *(uint4*)&Qs[row * QS_STRIDE + c4] = u;
    }

    float m0 = -INFINITY, m1 = -INFINITY, l0 = 0.f, l1 = 0.f;
    float oacc[8][4];
#pragma unroll
    for (int j = 0; j < 8; j++)
#pragma unroll
        for (int c = 0; c < 4; c++) oacc[j][c] = 0.f;

    for (int kt = 0; kt <= qt; kt++) {
        const int k0 = kt * 64;
        __syncthreads();   // prior iter done with Ks/Vs/Ps (and Q ready, 1st iter)
#pragma unroll
        for (int it = 0; it < 8; it++) {
            int i   = tid + it * 128;
            int row = i >> 4;
            int c4  = (i & 15) << 2;
            float4 kv = *(const float4*)&g_K[base + (size_t)(k0 + row) * DHD + c4];
            uint4 uk = { f2tf(kv.x), f2tf(kv.y), f2tf(kv.z), f2tf(kv.w) };
            *(uint4*)&Ks[row * QS_STRIDE + c4] = uk;
            float4 vv = *(const float4*)&g_V[base + (size_t)(k0 + row) * DHD + c4];
            uint4 uv = { f2tf(vv.x), f2tf(vv.y), f2tf(vv.z), f2tf(vv.w) };
            *(uint4*)&Vs[row * VS_STRIDE + c4] = uv;
        }
        __syncthreads();

        // ---- S = Q K^T (64x64), per-warp 16 rows ----
        float sacc[8][4];
#pragma unroll
        for (int j = 0; j < 8; j++)
#pragma unroll
            for (int c = 0; c < 4; c++) sacc[j][c] = 0.f;

#pragma unroll
        for (int kk = 0; kk < 8; kk++) {
            unsigned a[4];
            a[0] = Qs[(rw + g)     * QS_STRIDE + kk * 8 + t];
            a[1] = Qs[(rw + g + 8) * QS_STRIDE + kk * 8 + t];
            a[2] = Qs[(rw + g)     * QS_STRIDE + kk * 8 + t + 4];
            a[3] = Qs[(rw + g + 8) * QS_STRIDE + kk * 8 + t + 4];
#pragma unroll
            for (int j = 0; j < 8; j++) {
                unsigned bb[2];
                bb[0] = Ks[(j * 8 + g) * QS_STRIDE + kk * 8 + t];
                bb[1] = Ks[(j * 8 + g) * QS_STRIDE + kk * 8 + t + 4];
                mma_tf32(sacc[j], a, bb);
            }
        }

        // ---- causal mask on diagonal tile ----
        if (kt == qt) {
            const int r0 = rw + g, r1 = r0 + 8;
#pragma unroll
            for (int j = 0; j < 8; j++) {
                int cb = j * 8 + 2 * t;
                if (cb     > r0) sacc[j][0] = -INFINITY;
                if (cb + 1 > r0) sacc[j][1] = -INFINITY;
                if (cb     > r1) sacc[j][2] = -INFINITY;
                if (cb + 1 > r1) sacc[j][3] = -INFINITY;
            }
        }

        // ---- online softmax (rows g and g+8 of this warp) ----
        float mt0 = -INFINITY, mt1 = -INFINITY;
#pragma unroll
        for (int j = 0; j < 8; j++) {
            mt0 = fmaxf(mt0, fmaxf(sacc[j][0], sacc[j][1]));
            mt1 = fmaxf(mt1, fmaxf(sacc[j][2], sacc[j][3]));
        }
        mt0 = fmaxf(mt0, __shfl_xor_sync(0xffffffffu, mt0, 1));
        mt0 = fmaxf(mt0, __shfl_xor_sync(0xffffffffu, mt0, 2));
        mt1 = fmaxf(mt1, __shfl_xor_sync(0xffffffffu, mt1, 1));
        mt1 = fmaxf(mt1, __shfl_xor_sync(0xffffffffu, mt1, 2));

        float mn0 = fmaxf(m0, mt0), mn1 = fmaxf(m1, mt1);
        float cor0 = __expf(m0 - mn0), cor1 = __expf(m1 - mn1);

        float ls0 = 0.f, ls1 = 0.f;
#pragma unroll
        for (int j = 0; j < 8; j++) {
            float p00 = __expf(sacc[j][0] - mn0);
            float p01 = __expf(sacc[j][1] - mn0);
            float p10 = __expf(sacc[j][2] - mn1);
            float p11 = __expf(sacc[j][3] - mn1);
            ls0 += p00 + p01;
            ls1 += p10 + p11;
            Ps[(rw + g)     * QS_STRIDE + j * 8 + 2 * t]     = f2tf(p00);
            Ps[(rw + g)     * QS_STRIDE + j * 8 + 2 * t + 1] = f2tf(p01);
            Ps[(rw + g + 8) * QS_STRIDE + j * 8 + 2 * t]     = f2tf(p10);
            Ps[(rw + g + 8) * QS_STRIDE + j * 8 + 2 * t + 1] = f2tf(p11);
        }
        ls0 += __shfl_xor_sync(0xffffffffu, ls0, 1);
        ls0 += __shfl_xor_sync(0xffffffffu, ls0, 2);
        ls1 += __shfl_xor_sync(0xffffffffu, ls1, 1);
        ls1 += __shfl_xor_sync(0xffffffffu, ls1, 2);

        l0 = l0 * cor0 + ls0;  m0 = mn0;
        l1 = l1 * cor1 + ls1;  m1 = mn1;
#pragma unroll
        for (int j = 0; j < 8; j++) {
            oacc[j][0] *= cor0; oacc[j][1] *= cor0;
            oacc[j][2] *= cor1; oacc[j][3] *= cor1;
        }
        __syncwarp();   // P rows of this warp visible to its own lanes

        // ---- O += P V ----
#pragma unroll
        for (int kk = 0; kk < 8; kk++) {
            unsigned a[4];
            a[0] = Ps[(rw + g)     * QS_STRIDE + kk * 8 + t];
            a[1] = Ps[(rw + g + 8) * QS_STRIDE + kk * 8 + t];
            a[2] = Ps[(rw + g)     * QS_STRIDE + kk * 8 + t + 4];
            a[3] = Ps[(rw + g + 8) * QS_STRIDE + kk * 8 + t + 4];
#pragma unroll
            for (int j = 0; j < 8; j++) {
                unsigned bb[2];
                bb[0] = Vs[(kk * 8 + t)     * VS_STRIDE + j * 8 + g];
                bb[1] = Vs[(kk * 8 + t + 4) * VS_STRIDE + j * 8 + g];
                mma_tf32(oacc[j], a, bb);
            }
        }
    }

    // ---- normalize and write to g_O [B,T,C] ----
    const float inv0 = 1.0f / l0, inv1 = 1.0f / l1;
    const int qrow = q0 + rw + g;
    const size_t ob0 = ((size_t)b * TT + qrow)     * CC + h * DHD;
    const size_t ob1 = ((size_t)b * TT + qrow + 8) * CC + h * DHD;
#pragma unroll
    for (int j = 0; j < 8; j++) {
        int c = j * 8 + 2 * t;
        *(float2*)&O[ob0 + c] = make_float2(oacc[j][0] * inv0, oacc[j][1] * inv0);
        *(float2*)&O[ob1 + c] = make_float2(oacc[j][2] * inv1, oacc[j][3] * inv1);
    }
}

// ---------------------------------------------------------------------------
extern "C" void kernel_launch(void* const* d_in, const int* in_sizes, int n_in,
                              void* d_out, int out_size)
{
    const float* x     = (const float*)d_in[0];   // [4,2048,1024]
    const float* W_qkv = (const float*)d_in[1];   // [1024,3072]
    const float* b_qkv = (const float*)d_in[2];   // [3072]
    const float* W_out = (const float*)d_in[3];   // [1024,1024]
    const float* b_out = (const float*)d_in[4];   // [1024]
    float* out = (float*)d_out;                   // [4,2048,1024]

    void *pQ, *pK, *pV, *pO;
    cudaGetSymbolAddress(&pQ, g_Q);
    cudaGetSymbolAddress(&pK, g_K);
    cudaGetSymbolAddress(&pV, g_V);
    cudaGetSymbolAddress(&pO, g_O);

    cudaFuncSetAttribute(attn_tc, cudaFuncAttributeMaxDynamicSharedMemorySize,
                         ATT_SMEM_BYTES);

    // 1) QKV projection + scatter to [B,H,T,Dh]
    {
        dim3 grid(3072 / 128, MM / 128);
        sgemm_tc<3072, 1><<<grid, 256>>>(x, W_qkv, b_qkv,
                                         (float*)pQ, (float*)pK, (float*)pV);
    }
    // 2) Causal flash attention (tf32 tensor cores) -> g_O [B,T,C]
    {
        dim3 grid(TT / 64, BB * HH);
        attn_tc<<<grid, 128, ATT_SMEM_BYTES>>>((float*)pO);
    }
    // 3) Output projection -> d_out
    {
        dim3 grid(1024 / 128, MM / 128);
        sgemm_tc<1024, 0><<<grid, 256>>>((const float*)pO, W_out, b_out,
                                         out, nullptr, nullptr);
    }
}

// round 7
// speedup vs baseline: 7.7127x; 2.7994x over previous
#include <cuda_runtime.h>
#include <cuda_fp16.h>
#include <math.h>
#include <stdint.h>

// Problem constants
#define BB 4
#define TT 2048
#define CC 1024
#define HH 16
#define DHD 64
#define MM (BB*TT)          // 8192 rows

// Scratch (allocation-free rule: __device__ globals)
__device__ __half g_x16[MM*CC];          // x in fp16
__device__ __half g_Q16[BB*HH*TT*DHD];   // Q [B,H,T,Dh] fp16, pre-scaled by 1/8
__device__ __half g_K16[BB*HH*TT*DHD];
__device__ __half g_V16[BB*HH*TT*DHD];
__device__ __half g_O16[MM*CC];          // attention out [B,T,C] fp16
__device__ __half g_Wq16[3072*1024];     // W_qkv^T [N,K] fp16
__device__ __half g_Wo16[1024*1024];     // W_out^T [N,K] fp16

// ---------------------------------------------------------------------------
// helpers
// ---------------------------------------------------------------------------
__device__ __forceinline__ uint32_t smem_u32(const void* p) {
    uint32_t a;
    asm("{ .reg .u64 t; cvta.to.shared.u64 t, %1; cvt.u32.u64 %0, t; }"
        : "=r"(a) : "l"(p));
    return a;
}
__device__ __forceinline__ void cp16(uint32_t s, const void* g) {
    asm volatile("cp.async.cg.shared.global [%0], [%1], 16;" :: "r"(s), "l"(g));
}
#define CP_COMMIT() asm volatile("cp.async.commit_group;" ::: "memory")
#define CP_WAIT(n)  asm volatile("cp.async.wait_group %0;" :: "n"(n) : "memory")

__device__ __forceinline__ void mma_f16(float c[4], const unsigned a[4],
                                        const unsigned b[2]) {
    asm volatile(
        "mma.sync.aligned.m16n8k16.row.col.f32.f16.f16.f32 "
        "{%0,%1,%2,%3},{%4,%5,%6,%7},{%8,%9},{%0,%1,%2,%3};"
        : "+f"(c[0]), "+f"(c[1]), "+f"(c[2]), "+f"(c[3])
        : "r"(a[0]), "r"(a[1]), "r"(a[2]), "r"(a[3]), "r"(b[0]), "r"(b[1]));
}
__device__ __forceinline__ unsigned h2u(float a, float b) {
    __half2 h = __floats2half2_rn(a, b);
    return *(unsigned*)&h;
}

// ---------------------------------------------------------------------------
// Pre-pass kernels
// ---------------------------------------------------------------------------
__global__ __launch_bounds__(256)
void f2h_k(const float* __restrict__ src, __half* __restrict__ dst)
{
    int i = blockIdx.x * 256 + threadIdx.x;     // handles 8 floats
    float4 a = ((const float4*)src)[2 * i];
    float4 b = ((const float4*)src)[2 * i + 1];
    uint4 o;
    o.x = h2u(a.x, a.y); o.y = h2u(a.z, a.w);
    o.z = h2u(b.x, b.y); o.w = h2u(b.z, b.w);
    ((uint4*)dst)[i] = o;
}

// transpose + fp16: src[R][C] f32 -> dst[C][R] fp16
__global__ __launch_bounds__(256)
void transpose_h(const float* __restrict__ src, __half* __restrict__ dst,
                 int R, int C)
{
    __shared__ float tile[32][33];
    const int bx = blockIdx.x * 32;   // src col base
    const int by = blockIdx.y * 32;   // src row base
    const int tx = threadIdx.x & 31;
    const int ty = threadIdx.x >> 5;  // 0..7
#pragma unroll
    for (int i = 0; i < 32; i += 8)
        tile[ty + i][tx] = src[(size_t)(by + ty + i) * C + bx + tx];
    __syncthreads();
#pragma unroll
    for (int i = 0; i < 32; i += 8)
        dst[(size_t)(bx + ty + i) * R + by + tx] = __float2half(tile[tx][ty + i]);
}

// ---------------------------------------------------------------------------
// fp16 tensor-core GEMM: C[M,N] = A[M,1024] @ Bt[N,1024]^T + bias
// 128x128 tile, BK=32 fp16 (2 x k16), cp.async 3-stage pipeline.
// Smem rows padded to 20 words (32 fp16 data + 4 words) -> conflict-free
// fragment LDS (20g mod 32 covers all multiples of 4).
// 8 warps: 2 M-groups x 4 N-groups, warp tile 64x32.
// MODE 0: fp32 store to O0[M,N].
// MODE 1: QKV scatter -> fp16 O0/O1/O2 as [B,H,T,Dh], Q scaled by 0.125.
// ---------------------------------------------------------------------------
#define LSTR 20
#define TILE_WORDS (128*LSTR)
#define STG_WORDS (2*TILE_WORDS)
#define PIPE 3
#define GEMM_SMEM (PIPE*STG_WORDS*4)

template<int N, int MODE>
__global__ __launch_bounds__(256, 2)
void gemm16(const __half* __restrict__ A, const __half* __restrict__ Bt,
            const float* __restrict__ bias,
            void* __restrict__ O0, void* __restrict__ O1, void* __restrict__ O2)
{
    extern __shared__ uint32_t sw[];
    const int tid  = threadIdx.x;
    const int w    = tid >> 5;
    const int lane = tid & 31;
    const int g    = lane >> 2;
    const int t    = lane & 3;
    const int wm   = (w >> 2) * 64;
    const int wn   = (w & 3) * 32;
    const int bm   = blockIdx.y * 128;
    const int bn   = blockIdx.x * 128;
    const uint32_t smem_base = smem_u32(sw);

    const int irow = tid >> 2;        // 0..63? no: tid>>2 -> 0..63; with r offset
    const int ic   = tid & 3;

    // issue cp.async for one 32-wide K slab into stage st
    auto issue = [&](int slab, int st) {
        const int k0 = slab * 32;
        const uint32_t baseA = smem_base + (uint32_t)st * STG_WORDS * 4;
        const uint32_t baseB = baseA + TILE_WORDS * 4;
#pragma unroll
        for (int r = 0; r < 2; r++) {
            const int row = irow + r * 64;
            cp16(baseA + (row * LSTR + ic * 4) * 4,
                 &A[(size_t)(bm + row) * 1024 + k0 + ic * 8]);
            cp16(baseB + (row * LSTR + ic * 4) * 4,
                 &Bt[(size_t)(bn + row) * 1024 + k0 + ic * 8]);
        }
        CP_COMMIT();
    };

    issue(0, 0); issue(1, 1); issue(2, 2);

    float acc[4][4][4];
#pragma unroll
    for (int mi = 0; mi < 4; mi++)
#pragma unroll
        for (int ni = 0; ni < 4; ni++)
#pragma unroll
            for (int c = 0; c < 4; c++) acc[mi][ni][c] = 0.f;

    for (int s = 0; s < 32; s++) {
        CP_WAIT(PIPE - 1);
        __syncthreads();
        const uint32_t* As = sw + (s % PIPE) * STG_WORDS;
        const uint32_t* Bs = As + TILE_WORDS;
#pragma unroll
        for (int kk = 0; kk < 2; kk++) {
            unsigned a[4][4];
#pragma unroll
            for (int mi = 0; mi < 4; mi++) {
                const int rm = wm + mi * 16;
                a[mi][0] = As[(rm + g)     * LSTR + kk * 8 + t];
                a[mi][1] = As[(rm + g + 8) * LSTR + kk * 8 + t];
                a[mi][2] = As[(rm + g)     * LSTR + kk * 8 + t + 4];
                a[mi][3] = As[(rm + g + 8) * LSTR + kk * 8 + t + 4];
            }
#pragma unroll
            for (int ni = 0; ni < 4; ni++) {
                const int nb = wn + ni * 8;
                unsigned b[2];
                b[0] = Bs[(nb + g) * LSTR + kk * 8 + t];
                b[1] = Bs[(nb + g) * LSTR + kk * 8 + t + 4];
#pragma unroll
                for (int mi = 0; mi < 4; mi++)
                    mma_f16(acc[mi][ni], a[mi], b);
            }
        }
        __syncthreads();
        if (s + PIPE < 32) issue(s + PIPE, s % PIPE);
    }

    // epilogue
#pragma unroll
    for (int mi = 0; mi < 4; mi++) {
#pragma unroll
        for (int ni = 0; ni < 4; ni++) {
            const int r0 = bm + wm + mi * 16 + g;
            const int c0 = bn + wn + ni * 8 + 2 * t;
            const float b0 = bias[c0], b1 = bias[c0 + 1];
            float v00 = acc[mi][ni][0] + b0, v01 = acc[mi][ni][1] + b1;
            float v10 = acc[mi][ni][2] + b0, v11 = acc[mi][ni][3] + b1;
            if (MODE == 0) {
                float* O = (float*)O0;
                *(float2*)&O[(size_t)r0 * N + c0]       = make_float2(v00, v01);
                *(float2*)&O[(size_t)(r0 + 8) * N + c0] = make_float2(v10, v11);
            } else {
                const int sec = c0 >> 10;          // 0=q,1=k,2=v
                const int cc  = c0 & 1023;
                const int h   = cc >> 6;
                const int d   = cc & 63;
                __half* dst = (sec == 0) ? (__half*)O0
                            : (sec == 1) ? (__half*)O1 : (__half*)O2;
                const float sc = (sec == 0) ? 0.125f : 1.0f;
                {
                    const int m = r0;
                    const size_t o = (((size_t)((m >> 11) * HH + h)) * TT + (m & 2047)) * DHD + d;
                    *(unsigned*)&dst[o] = h2u(v00 * sc, v01 * sc);
                }
                {
                    const int m = r0 + 8;
                    const size_t o = (((size_t)((m >> 11) * HH + h)) * TT + (m & 2047)) * DHD + d;
                    *(unsigned*)&dst[o] = h2u(v10 * sc, v11 * sc);
                }
            }
        }
    }
}

// ---------------------------------------------------------------------------
// Causal flash attention, fp16 mma m16n8k16.
// Block = 128 queries of one (b,h). 256 threads = 8 warps x 16 rows.
// Smem word stride 36 (==4 mod 8) -> conflict-free fragment LDS.
// Vt holds V transposed [d][key] so B fragments pack key-pairs per word.
// ---------------------------------------------------------------------------
#define AST 36
#define ATT_WORDS ((128 + 64 + 128 + 64) * AST)
#define ATT_SMEM_BYTES (ATT_WORDS * 4)

__global__ __launch_bounds__(256)
void attn16(__half* __restrict__ O)
{
    extern __shared__ uint32_t sm[];
    uint32_t* Qs = sm;                       // [128][36]
    uint32_t* Ks = Qs + 128 * AST;           // [64][36]
    uint32_t* Ps = Ks + 64 * AST;            // [128][36]
    uint32_t* Vt = Ps + 128 * AST;           // [64][36]  V^T: [d][key]

    const int tid  = threadIdx.x;
    const int w    = tid >> 5;
    const int lane = tid & 31;
    const int g    = lane >> 2;
    const int t    = lane & 3;
    const int bh   = blockIdx.y;             // 0..63
    const int qt   = blockIdx.x;             // 0..15
    const int b    = bh >> 4;
    const int h    = bh & 15;
    const size_t base = (size_t)bh * TT * DHD;
    const int q0   = qt * 128;
    const int rw   = w * 16;

    // Load Q tile (already scaled in GEMM epilogue): 128 rows x 8 uint4
#pragma unroll
    for (int it = 0; it < 4; it++) {
        const int i   = tid + it * 256;
        const int row = i >> 3;
        const int c   = i & 7;
        *(uint4*)&Qs[row * AST + c * 4] =
            *(const uint4*)&g_Q16[base + (size_t)(q0 + row) * DHD + c * 8];
    }

    float m0 = -INFINITY, m1 = -INFINITY, l0 = 0.f, l1 = 0.f;
    float oacc[8][4];
#pragma unroll
    for (int j = 0; j < 8; j++)
#pragma unroll
        for (int c = 0; c < 4; c++) oacc[j][c] = 0.f;

    const int ktmax = 2 * qt + 1;
    for (int kt = 0; kt <= ktmax; kt++) {
        const int k0g = kt * 64;
        __syncthreads();
        // K tile: straight copy. V tile: transpose into Vt with bank rotation.
#pragma unroll
        for (int it = 0; it < 2; it++) {
            const int i   = tid + it * 256;
            const int row = i >> 3;          // key 0..63
            const int c   = i & 7;
            const size_t go = base + (size_t)(k0g + row) * DHD + c * 8;
            *(uint4*)&Ks[row * AST + c * 4] = *(const uint4*)&g_K16[go];
            uint4 vv = *(const uint4*)&g_V16[go];
            unsigned vw[4] = { vv.x, vv.y, vv.z, vv.w };
            const __half* hp = (const __half*)vw;
            const int d0  = c * 8;
            const int rot0 = c;              // d0>>3
            __half* VtH = (__half*)Vt;
#pragma unroll
            for (int e = 0; e < 8; e++) {
                const int sel = (e + rot0) & 7;
                VtH[(d0 + sel) * (2 * AST) + row] = hp[sel];
            }
        }
        __syncthreads();

        // ---- S = Q K^T (warp rows rw..rw+15, 64 keys) ----
        float sacc[8][4];
#pragma unroll
        for (int j = 0; j < 8; j++)
#pragma unroll
            for (int c = 0; c < 4; c++) sacc[j][c] = 0.f;

#pragma unroll
        for (int kk = 0; kk < 4; kk++) {
            unsigned a[4];
            a[0] = Qs[(rw + g)     * AST + kk * 8 + t];
            a[1] = Qs[(rw + g + 8) * AST + kk * 8 + t];
            a[2] = Qs[(rw + g)     * AST + kk * 8 + t + 4];
            a[3] = Qs[(rw + g + 8) * AST + kk * 8 + t + 4];
#pragma unroll
            for (int j = 0; j < 8; j++) {
                unsigned bb[2];
                bb[0] = Ks[(j * 8 + g) * AST + kk * 8 + t];
                bb[1] = Ks[(j * 8 + g) * AST + kk * 8 + t + 4];
                mma_f16(sacc[j], a, bb);
            }
        }

        // ---- causal mask (only when tile can cross this warp's diagonal) ----
        if (k0g + 63 > q0 + rw) {
            const int gr0 = q0 + rw + g, gr1 = gr0 + 8;
#pragma unroll
            for (int j = 0; j < 8; j++) {
                const int gc = k0g + j * 8 + 2 * t;
                if (gc     > gr0) sacc[j][0] = -INFINITY;
                if (gc + 1 > gr0) sacc[j][1] = -INFINITY;
                if (gc     > gr1) sacc[j][2] = -INFINITY;
                if (gc + 1 > gr1) sacc[j][3] = -INFINITY;
            }
        }

        // ---- online softmax (rows rw+g, rw+g+8) ----
        float mt0 = -INFINITY, mt1 = -INFINITY;
#pragma unroll
        for (int j = 0; j < 8; j++) {
            mt0 = fmaxf(mt0, fmaxf(sacc[j][0], sacc[j][1]));
            mt1 = fmaxf(mt1, fmaxf(sacc[j][2], sacc[j][3]));
        }
        mt0 = fmaxf(mt0, __shfl_xor_sync(0xffffffffu, mt0, 1));
        mt0 = fmaxf(mt0, __shfl_xor_sync(0xffffffffu, mt0, 2));
        mt1 = fmaxf(mt1, __shfl_xor_sync(0xffffffffu, mt1, 1));
        mt1 = fmaxf(mt1, __shfl_xor_sync(0xffffffffu, mt1, 2));

        const float mn0 = fmaxf(m0, mt0), mn1 = fmaxf(m1, mt1);
        const float cor0 = __expf(m0 - mn0), cor1 = __expf(m1 - mn1);

        float ls0 = 0.f, ls1 = 0.f;
#pragma unroll
        for (int j = 0; j < 8; j++) {
            const float p00 = __expf(sacc[j][0] - mn0);
            const float p01 = __expf(sacc[j][1] - mn0);
            const float p10 = __expf(sacc[j][2] - mn1);
            const float p11 = __expf(sacc[j][3] - mn1);
            ls0 += p00 + p01;
            ls1 += p10 + p11;
            Ps[(rw + g)     * AST + j * 4 + t] = h2u(p00, p01);
            Ps[(rw + g + 8) * AST + j * 4 + t] = h2u(p10, p11);
        }
        ls0 += __shfl_xor_sync(0xffffffffu, ls0, 1);
        ls0 += __shfl_xor_sync(0xffffffffu, ls0, 2);
        ls1 += __shfl_xor_sync(0xffffffffu, ls1, 1);
        ls1 += __shfl_xor_sync(0xffffffffu, ls1, 2);

        l0 = l0 * cor0 + ls0;  m0 = mn0;
        l1 = l1 * cor1 + ls1;  m1 = mn1;
#pragma unroll
        for (int j = 0; j < 8; j++) {
            oacc[j][0] *= cor0; oacc[j][1] *= cor0;
            oacc[j][2] *= cor1; oacc[j][3] *= cor1;
        }
        __syncwarp();   // this warp's P rows visible to itself

        // ---- O += P V ---- (A = P rows, B = Vt[d][key])
#pragma unroll
        for (int kk = 0; kk < 4; kk++) {
            unsigned a[4];
            a[0] = Ps[(rw + g)     * AST + kk * 8 + t];
            a[1] = Ps[(rw + g + 8) * AST + kk * 8 + t];
            a[2] = Ps[(rw + g)     * AST + kk * 8 + t + 4];
            a[3] = Ps[(rw + g + 8) * AST + kk * 8 + t + 4];
#pragma unroll
            for (int j = 0; j < 8; j++) {
                unsigned bb[2];
                bb[0] = Vt[(j * 8 + g) * AST + kk * 8 + t];
                bb[1] = Vt[(j * 8 + g) * AST + kk * 8 + t + 4];
                mma_f16(oacc[j], a, bb);
            }
        }
    }

    // ---- normalize, write fp16 g_O [B,T,C] ----
    const float inv0 = 1.0f / l0, inv1 = 1.0f / l1;
    const int qrow = q0 + rw + g;
    const size_t ob0 = ((size_t)b * TT + qrow)     * CC + h * DHD;
    const size_t ob1 = ((size_t)b * TT + qrow + 8) * CC + h * DHD;
#pragma unroll
    for (int j = 0; j < 8; j++) {
        const int c = j * 8 + 2 * t;
        *(unsigned*)&O[ob0 + c] = h2u(oacc[j][0] * inv0, oacc[j][1] * inv0);
        *(unsigned*)&O[ob1 + c] = h2u(oacc[j][2] * inv1, oacc[j][3] * inv1);
    }
}

// ---------------------------------------------------------------------------
extern "C" void kernel_launch(void* const* d_in, const int* in_sizes, int n_in,
                              void* d_out, int out_size)
{
    const float* x     = (const float*)d_in[0];   // [4,2048,1024]
    const float* W_qkv = (const float*)d_in[1];   // [1024,3072]
    const float* b_qkv = (const float*)d_in[2];   // [3072]
    const float* W_out = (const float*)d_in[3];   // [1024,1024]
    const float* b_out = (const float*)d_in[4];   // [1024]
    float* out = (float*)d_out;                   // [4,2048,1024]

    void *pX, *pQ, *pK, *pV, *pO, *pWq, *pWo;
    cudaGetSymbolAddress(&pX,  g_x16);
    cudaGetSymbolAddress(&pQ,  g_Q16);
    cudaGetSymbolAddress(&pK,  g_K16);
    cudaGetSymbolAddress(&pV,  g_V16);
    cudaGetSymbolAddress(&pO,  g_O16);
    cudaGetSymbolAddress(&pWq, g_Wq16);
    cudaGetSymbolAddress(&pWo, g_Wo16);

    cudaFuncSetAttribute(attn16, cudaFuncAttributeMaxDynamicSharedMemorySize,
                         ATT_SMEM_BYTES);
    cudaFuncSetAttribute(gemm16<3072,1>,
                         cudaFuncAttributeMaxDynamicSharedMemorySize, GEMM_SMEM);
    cudaFuncSetAttribute(gemm16<1024,0>,
                         cudaFuncAttributeMaxDynamicSharedMemorySize, GEMM_SMEM);

    // 0) Pre-pass: x -> fp16, weights -> fp16 transposed [N,K]
    f2h_k<<<(MM * CC) / (256 * 8), 256>>>(x, (__half*)pX);
    transpose_h<<<dim3(3072/32, 1024/32), 256>>>(W_qkv, (__half*)pWq, 1024, 3072);
    transpose_h<<<dim3(1024/32, 1024/32), 256>>>(W_out, (__half*)pWo, 1024, 1024);

    // 1) QKV projection (fp16 mma + cp.async) + scatter to [B,H,T,Dh]
    {
        dim3 grid(3072 / 128, MM / 128);
        gemm16<3072,1><<<grid, 256, GEMM_SMEM>>>((const __half*)pX,
                                                 (const __half*)pWq, b_qkv,
                                                 pQ, pK, pV);
    }
    // 2) Causal flash attention (fp16 mma) -> g_O16 [B,T,C]
    {
        dim3 grid(TT / 128, BB * HH);
        attn16<<<grid, 256, ATT_SMEM_BYTES>>>((__half*)pO);
    }
    // 3) Output projection -> d_out (fp32)
    {
        dim3 grid(1024 / 128, MM / 128);
        gemm16<1024,0><<<grid, 256, GEMM_SMEM>>>((const __half*)pO,
                                                 (const __half*)pWo, b_out,
                                                 out, nullptr, nullptr);
    }
}

// round 9
// speedup vs baseline: 8.6832x; 1.1258x over previous
#include <cuda_runtime.h>
#include <cuda_fp16.h>
#include <math.h>
#include <stdint.h>

// Problem constants
#define BB 4
#define TT 2048
#define CC 1024
#define HH 16
#define DHD 64
#define MM (BB*TT)          // 8192 rows

// Scratch (allocation-free rule: __device__ globals)
__device__ __half g_x16[MM*CC];          // x in fp16
__device__ __half g_Q16[BB*HH*TT*DHD];   // Q [B,H,T,Dh] fp16, pre-scaled by 1/8
__device__ __half g_K16[BB*HH*TT*DHD];
__device__ __half g_V16[BB*HH*TT*DHD];
__device__ __half g_O16[MM*CC];          // attention out [B,T,C] fp16
__device__ __half g_Wq16[3072*1024];     // W_qkv^T [N,K] fp16
__device__ __half g_Wo16[1024*1024];     // W_out^T [N,K] fp16

// ---------------------------------------------------------------------------
// helpers
// ---------------------------------------------------------------------------
__device__ __forceinline__ uint32_t smem_u32(const void* p) {
    uint32_t a;
    asm("{ .reg .u64 t; cvta.to.shared.u64 t, %1; cvt.u32.u64 %0, t; }"
        : "=r"(a) : "l"(p));
    return a;
}
__device__ __forceinline__ void cp16(uint32_t s, const void* g) {
    asm volatile("cp.async.cg.shared.global [%0], [%1], 16;" :: "r"(s), "l"(g));
}
#define CP_COMMIT() asm volatile("cp.async.commit_group;" ::: "memory")
#define CP_WAIT(n)  asm volatile("cp.async.wait_group %0;" :: "n"(n) : "memory")

__device__ __forceinline__ void mma_f16(float c[4], const unsigned a[4],
                                        const unsigned b0, const unsigned b1) {
    asm volatile(
        "mma.sync.aligned.m16n8k16.row.col.f32.f16.f16.f32 "
        "{%0,%1,%2,%3},{%4,%5,%6,%7},{%8,%9},{%0,%1,%2,%3};"
        : "+f"(c[0]), "+f"(c[1]), "+f"(c[2]), "+f"(c[3])
        : "r"(a[0]), "r"(a[1]), "r"(a[2]), "r"(a[3]), "r"(b0), "r"(b1));
}
__device__ __forceinline__ void ldsm4(unsigned r[4], uint32_t addr) {
    asm volatile("ldmatrix.sync.aligned.m8n8.x4.shared.b16 {%0,%1,%2,%3}, [%4];"
                 : "=r"(r[0]), "=r"(r[1]), "=r"(r[2]), "=r"(r[3]) : "r"(addr));
}
__device__ __forceinline__ unsigned h2u(float a, float b) {
    __half2 h = __floats2half2_rn(a, b);
    return *(unsigned*)&h;
}

// ---------------------------------------------------------------------------
// Pre-pass kernels
// ---------------------------------------------------------------------------
__global__ __launch_bounds__(256)
void f2h_k(const float* __restrict__ src, __half* __restrict__ dst)
{
    int i = blockIdx.x * 256 + threadIdx.x;     // handles 8 floats
    float4 a = ((const float4*)src)[2 * i];
    float4 b = ((const float4*)src)[2 * i + 1];
    uint4 o;
    o.x = h2u(a.x, a.y); o.y = h2u(a.z, a.w);
    o.z = h2u(b.x, b.y); o.w = h2u(b.z, b.w);
    ((uint4*)dst)[i] = o;
}

// transpose + fp16: src[R][C] f32 -> dst[C][R] fp16
__global__ __launch_bounds__(256)
void transpose_h(const float* __restrict__ src, __half* __restrict__ dst,
                 int R, int C)
{
    __shared__ float tile[32][33];
    const int bx = blockIdx.x * 32;
    const int by = blockIdx.y * 32;
    const int tx = threadIdx.x & 31;
    const int ty = threadIdx.x >> 5;
#pragma unroll
    for (int i = 0; i < 32; i += 8)
        tile[ty + i][tx] = src[(size_t)(by + ty + i) * C + bx + tx];
    __syncthreads();
#pragma unroll
    for (int i = 0; i < 32; i += 8)
        dst[(size_t)(bx + ty + i) * R + by + tx] = __float2half(tile[tx][ty + i]);
}

// ---------------------------------------------------------------------------
// fp16 tensor-core GEMM: C[M,N] = A[M,1024] @ Bt[N,1024]^T + bias
// 128x128 tile, BK=32 fp16 (2 x k16), cp.async 4-stage pipeline,
// ldmatrix.x4 fragment loads (6 ldsm + 16 mma per k16 step per warp).
// Smem rows: 20-word stride (conflict-free ldmatrix phases).
// 8 warps: 2 M-groups x 4 N-groups, warp tile 64x32.
// MODE 0: fp32 store.  MODE 1: QKV scatter -> fp16 [B,H,T,Dh], Q scaled 1/8.
// ---------------------------------------------------------------------------
#define LSTR 20
#define TILE_WORDS (128*LSTR)
#define STG_WORDS (2*TILE_WORDS)
#define PIPE 4
#define GEMM_SMEM (PIPE*STG_WORDS*4)

template<int N, int MODE>
__global__ __launch_bounds__(256, 2)
void gemm16(const __half* __restrict__ A, const __half* __restrict__ Bt,
            const float* __restrict__ bias,
            void* __restrict__ O0, void* __restrict__ O1, void* __restrict__ O2)
{
    extern __shared__ uint32_t sw[];
    const int tid  = threadIdx.x;
    const int w    = tid >> 5;
    const int lane = tid & 31;
    const int g    = lane >> 2;
    const int t    = lane & 3;
    const int wm   = (w >> 2) * 64;
    const int wn   = (w & 3) * 32;
    const int bm   = blockIdx.y * 128;
    const int bn   = blockIdx.x * 128;
    const uint32_t smem_base = smem_u32(sw);

    // ldmatrix lane addressing
    const int l7       = lane & 7;
    const int a_row_off = l7 + ((lane & 8) ? 8 : 0);
    const int a_col4    = ((lane >> 4) & 1) * 4;          // word offset 0 or 4
    const int sel       = lane >> 3;
    const int b_row_off = l7 + ((sel & 2) ? 8 : 0);
    const int b_col4    = (sel & 1) * 4;

    const int irow = tid >> 2;
    const int ic   = tid & 3;

    auto issue = [&](int slab, int st) {
        const int k0 = slab * 32;
        const uint32_t baseA = smem_base + (uint32_t)st * STG_WORDS * 4;
        const uint32_t baseB = baseA + TILE_WORDS * 4;
#pragma unroll
        for (int r = 0; r < 2; r++) {
            const int row = irow + r * 64;
            cp16(baseA + (row * LSTR + ic * 4) * 4,
                 &A[(size_t)(bm + row) * 1024 + k0 + ic * 8]);
            cp16(baseB + (row * LSTR + ic * 4) * 4,
                 &Bt[(size_t)(bn + row) * 1024 + k0 + ic * 8]);
        }
        CP_COMMIT();
    };

    issue(0, 0); issue(1, 1); issue(2, 2); issue(3, 3);

    float acc[4][4][4];
#pragma unroll
    for (int mi = 0; mi < 4; mi++)
#pragma unroll
        for (int ni = 0; ni < 4; ni++)
#pragma unroll
            for (int c = 0; c < 4; c++) acc[mi][ni][c] = 0.f;

    for (int s = 0; s < 32; s++) {
        CP_WAIT(PIPE - 1);
        __syncthreads();
        const uint32_t As_b = smem_base + (uint32_t)(s % PIPE) * STG_WORDS * 4;
        const uint32_t Bs_b = As_b + TILE_WORDS * 4;
#pragma unroll
        for (int kk = 0; kk < 2; kk++) {
            unsigned a[4][4];
#pragma unroll
            for (int mi = 0; mi < 4; mi++)
                ldsm4(a[mi], As_b + (((wm + mi * 16) + a_row_off) * LSTR
                                     + a_col4 + kk * 8) * 4);
            unsigned b[2][4];
#pragma unroll
            for (int nip = 0; nip < 2; nip++)
                ldsm4(b[nip], Bs_b + (((wn + nip * 16) + b_row_off) * LSTR
                                      + b_col4 + kk * 8) * 4);
#pragma unroll
            for (int nip = 0; nip < 2; nip++)
#pragma unroll
                for (int mi = 0; mi < 4; mi++) {
                    mma_f16(acc[mi][2 * nip],     a[mi], b[nip][0], b[nip][1]);
                    mma_f16(acc[mi][2 * nip + 1], a[mi], b[nip][2], b[nip][3]);
                }
        }
        __syncthreads();
        if (s + PIPE < 32) issue(s + PIPE, s % PIPE);
    }

    // epilogue
#pragma unroll
    for (int mi = 0; mi < 4; mi++) {
#pragma unroll
        for (int ni = 0; ni < 4; ni++) {
            const int r0 = bm + wm + mi * 16 + g;
            const int c0 = bn + wn + ni * 8 + 2 * t;
            const float b0 = bias[c0], b1 = bias[c0 + 1];
            float v00 = acc[mi][ni][0] + b0, v01 = acc[mi][ni][1] + b1;
            float v10 = acc[mi][ni][2] + b0, v11 = acc[mi][ni][3] + b1;
            if (MODE == 0) {
                float* O = (float*)O0;
                *(float2*)&O[(size_t)r0 * N + c0]       = make_float2(v00, v01);
                *(float2*)&O[(size_t)(r0 + 8) * N + c0] = make_float2(v10, v11);
            } else {
                const int sec = c0 >> 10;          // 0=q,1=k,2=v
                const int cc  = c0 & 1023;
                const int h   = cc >> 6;
                const int d   = cc & 63;
                __half* dst = (sec == 0) ? (__half*)O0
                            : (sec == 1) ? (__half*)O1 : (__half*)O2;
                const float sc = (sec == 0) ? 0.125f : 1.0f;
                {
                    const int m = r0;
                    const size_t o = (((size_t)((m >> 11) * HH + h)) * TT + (m & 2047)) * DHD + d;
                    *(unsigned*)&dst[o] = h2u(v00 * sc, v01 * sc);
                }
                {
                    const int m = r0 + 8;
                    const size_t o = (((size_t)((m >> 11) * HH + h)) * TT + (m & 2047)) * DHD + d;
                    *(unsigned*)&dst[o] = h2u(v10 * sc, v11 * sc);
                }
            }
        }
    }
}

// ---------------------------------------------------------------------------
// Causal flash attention, fp16 mma m16n8k16, ldmatrix fragments,
// P kept in registers (accumulator->A-fragment identity mapping).
// Block = 128 queries of one (b,h). 256 threads = 8 warps x 16 rows.
// Smem stride 36 words; Vt holds V^T [d][key] (bank-rotated scatter).
// ---------------------------------------------------------------------------
#define AST 36
#define ATT_WORDS ((128 + 64 + 64) * AST)
#define ATT_SMEM_BYTES (ATT_WORDS * 4)

__global__ __launch_bounds__(256)
void attn16(__half* __restrict__ O)
{
    extern __shared__ uint32_t sm[];
    uint32_t* Qs = sm;                       // [128][36]
    uint32_t* Ks = Qs + 128 * AST;           // [64][36]
    uint32_t* Vt = Ks + 64 * AST;            // [64][36]  V^T: [d][key]

    const int tid  = threadIdx.x;
    const int w    = tid >> 5;
    const int lane = tid & 31;
    const int g    = lane >> 2;
    const int t    = lane & 3;
    const int bh   = blockIdx.y;             // 0..63
    const int qt   = blockIdx.x;             // 0..15
    const int b    = bh >> 4;
    const int h    = bh & 15;
    const size_t base = (size_t)bh * TT * DHD;
    const int q0   = qt * 128;
    const int rw   = w * 16;

    const uint32_t qs_byte = smem_u32(Qs);
    const uint32_t ks_byte = smem_u32(Ks);
    const uint32_t vt_byte = smem_u32(Vt);

    const int l7        = lane & 7;
    const int a_row_off = l7 + ((lane & 8) ? 8 : 0);
    const int a_col4    = ((lane >> 4) & 1) * 4;
    const int sel       = lane >> 3;
    const int b_row_off = l7 + ((sel & 2) ? 8 : 0);
    const int b_col4    = (sel & 1) * 4;

    // Load Q tile (pre-scaled in GEMM epilogue): 128 rows x 8 uint4
#pragma unroll
    for (int it = 0; it < 4; it++) {
        const int i   = tid + it * 256;
        const int row = i >> 3;
        const int c   = i & 7;
        *(uint4*)&Qs[row * AST + c * 4] =
            *(const uint4*)&g_Q16[base + (size_t)(q0 + row) * DHD + c * 8];
    }

    float m0 = -INFINITY, m1 = -INFINITY, l0 = 0.f, l1 = 0.f;
    float oacc[8][4];
#pragma unroll
    for (int j = 0; j < 8; j++)
#pragma unroll
        for (int c = 0; c < 4; c++) oacc[j][c] = 0.f;

    const int ktmax = 2 * qt + 1;
    for (int kt = 0; kt <= ktmax; kt++) {
        const int k0g = kt * 64;
        __syncthreads();
        // K tile: straight copy. V tile: transpose into Vt with bank rotation.
#pragma unroll
        for (int it = 0; it < 2; it++) {
            const int i   = tid + it * 256;
            const int row = i >> 3;          // key 0..63
            const int c   = i & 7;
            const size_t go = base + (size_t)(k0g + row) * DHD + c * 8;
            *(uint4*)&Ks[row * AST + c * 4] = *(const uint4*)&g_K16[go];
            uint4 vv = *(const uint4*)&g_V16[go];
            unsigned vw[4] = { vv.x, vv.y, vv.z, vv.w };
            const __half* hp = (const __half*)vw;
            const int d0  = c * 8;
            __half* VtH = (__half*)Vt;
#pragma unroll
            for (int e = 0; e < 8; e++) {
                const int selr = (e + c) & 7;
                VtH[(d0 + selr) * (2 * AST) + row] = hp[selr];
            }
        }
        __syncthreads();

        // ---- S = Q K^T (warp rows rw..rw+15, 64 keys) ----
        float sacc[8][4];
#pragma unroll
        for (int j = 0; j < 8; j++)
#pragma unroll
            for (int c = 0; c < 4; c++) sacc[j][c] = 0.f;

#pragma unroll
        for (int kk = 0; kk < 4; kk++) {
            unsigned a[4];
            ldsm4(a, qs_byte + ((rw + a_row_off) * AST + a_col4 + kk * 8) * 4);
#pragma unroll
            for (int jp = 0; jp < 4; jp++) {
                unsigned bb[4];
                ldsm4(bb, ks_byte + ((jp * 16 + b_row_off) * AST
                                     + b_col4 + kk * 8) * 4);
                mma_f16(sacc[2 * jp],     a, bb[0], bb[1]);
                mma_f16(sacc[2 * jp + 1], a, bb[2], bb[3]);
            }
        }

        // ---- causal mask ----
        if (k0g + 63 > q0 + rw) {
            const int gr0 = q0 + rw + g, gr1 = gr0 + 8;
#pragma unroll
            for (int j = 0; j < 8; j++) {
                const int gc = k0g + j * 8 + 2 * t;
                if (gc     > gr0) sacc[j][0] = -INFINITY;
                if (gc + 1 > gr0) sacc[j][1] = -INFINITY;
                if (gc     > gr1) sacc[j][2] = -INFINITY;
                if (gc + 1 > gr1) sacc[j][3] = -INFINITY;
            }
        }

        // ---- online softmax (rows rw+g, rw+g+8) ----
        float mt0 = -INFINITY, mt1 = -INFINITY;
#pragma unroll
        for (int j = 0; j < 8; j++) {
            mt0 = fmaxf(mt0, fmaxf(sacc[j][0], sacc[j][1]));
            mt1 = fmaxf(mt1, fmaxf(sacc[j][2], sacc[j][3]));
        }
        mt0 = fmaxf(mt0, __shfl_xor_sync(0xffffffffu, mt0, 1));
        mt0 = fmaxf(mt0, __shfl_xor_sync(0xffffffffu, mt0, 2));
        mt1 = fmaxf(mt1, __shfl_xor_sync(0xffffffffu, mt1, 1));
        mt1 = fmaxf(mt1, __shfl_xor_sync(0xffffffffu, mt1, 2));

        const float mn0 = fmaxf(m0, mt0), mn1 = fmaxf(m1, mt1);
        const float cor0 = __expf(m0 - mn0), cor1 = __expf(m1 - mn1);

        float ls0 = 0.f, ls1 = 0.f;
#pragma unroll
        for (int j = 0; j < 8; j++) {
            sacc[j][0] = __expf(sacc[j][0] - mn0);
            sacc[j][1] = __expf(sacc[j][1] - mn0);
            sacc[j][2] = __expf(sacc[j][2] - mn1);
            sacc[j][3] = __expf(sacc[j][3] - mn1);
            ls0 += sacc[j][0] + sacc[j][1];
            ls1 += sacc[j][2] + sacc[j][3];
        }
        ls0 += __shfl_xor_sync(0xffffffffu, ls0, 1);
        ls0 += __shfl_xor_sync(0xffffffffu, ls0, 2);
        ls1 += __shfl_xor_sync(0xffffffffu, ls1, 1);
        ls1 += __shfl_xor_sync(0xffffffffu, ls1, 2);

        l0 = l0 * cor0 + ls0;  m0 = mn0;
        l1 = l1 * cor1 + ls1;  m1 = mn1;
#pragma unroll
        for (int j = 0; j < 8; j++) {
            oacc[j][0] *= cor0; oacc[j][1] *= cor0;
            oacc[j][2] *= cor1; oacc[j][3] *= cor1;
        }

        // ---- P accumulator -> A fragments (registers, no smem) ----
        unsigned pa[4][4];
#pragma unroll
        for (int kk = 0; kk < 4; kk++) {
            pa[kk][0] = h2u(sacc[2 * kk][0],     sacc[2 * kk][1]);
            pa[kk][1] = h2u(sacc[2 * kk][2],     sacc[2 * kk][3]);
            pa[kk][2] = h2u(sacc[2 * kk + 1][0], sacc[2 * kk + 1][1]);
            pa[kk][3] = h2u(sacc[2 * kk + 1][2], sacc[2 * kk + 1][3]);
        }

        // ---- O += P V ---- (B from Vt[d][key] via ldmatrix)
#pragma unroll
        for (int kk = 0; kk < 4; kk++) {
#pragma unroll
            for (int jp = 0; jp < 4; jp++) {
                unsigned bb[4];
                ldsm4(bb, vt_byte + ((jp * 16 + b_row_off) * AST
                                     + b_col4 + kk * 8) * 4);
                mma_f16(oacc[2 * jp],     pa[kk], bb[0], bb[1]);
                mma_f16(oacc[2 * jp + 1], pa[kk], bb[2], bb[3]);
            }
        }
    }

    // ---- normalize, write fp16 g_O [B,T,C] ----
    const float inv0 = 1.0f / l0, inv1 = 1.0f / l1;
    const int qrow = q0 + rw + g;
    const size_t ob0 = ((size_t)b * TT + qrow)     * CC + h * DHD;
    const size_t ob1 = ((size_t)b * TT + qrow + 8) * CC + h * DHD;
#pragma unroll
    for (int j = 0; j < 8; j++) {
        const int c = j * 8 + 2 * t;
        *(unsigned*)&O[ob0 + c] = h2u(oacc[j][0] * inv0, oacc[j][1] * inv0);
        *(unsigned*)&O[ob1 + c] = h2u(oacc[j][2] * inv1, oacc[j][3] * inv1);
    }
}

// ---------------------------------------------------------------------------
extern "C" void kernel_launch(void* const* d_in, const int* in_sizes, int n_in,
                              void* d_out, int out_size)
{
    const float* x     = (const float*)d_in[0];   // [4,2048,1024]
    const float* W_qkv = (const float*)d_in[1];   // [1024,3072]
    const float* b_qkv = (const float*)d_in[2];   // [3072]
    const float* W_out = (const float*)d_in[3];   // [1024,1024]
    const float* b_out = (const float*)d_in[4];   // [1024]
    float* out = (float*)d_out;                   // [4,2048,1024]

    void *pX, *pQ, *pK, *pV, *pO, *pWq, *pWo;
    cudaGetSymbolAddress(&pX,  g_x16);
    cudaGetSymbolAddress(&pQ,  g_Q16);
    cudaGetSymbolAddress(&pK,  g_K16);
    cudaGetSymbolAddress(&pV,  g_V16);
    cudaGetSymbolAddress(&pO,  g_O16);
    cudaGetSymbolAddress(&pWq, g_Wq16);
    cudaGetSymbolAddress(&pWo, g_Wo16);

    cudaFuncSetAttribute(attn16, cudaFuncAttributeMaxDynamicSharedMemorySize,
                         ATT_SMEM_BYTES);
    cudaFuncSetAttribute(gemm16<3072,1>,
                         cudaFuncAttributeMaxDynamicSharedMemorySize, GEMM_SMEM);
    cudaFuncSetAttribute(gemm16<1024,0>,
                         cudaFuncAttributeMaxDynamicSharedMemorySize, GEMM_SMEM);

    // 0) Pre-pass: x -> fp16, weights -> fp16 transposed [N,K]
    f2h_k<<<(MM * CC) / (256 * 8), 256>>>(x, (__half*)pX);
    transpose_h<<<dim3(3072/32, 1024/32), 256>>>(W_qkv, (__half*)pWq, 1024, 3072);
    transpose_h<<<dim3(1024/32, 1024/32), 256>>>(W_out, (__half*)pWo, 1024, 1024);

    // 1) QKV projection (fp16 mma + cp.async + ldmatrix)
    {
        dim3 grid(3072 / 128, MM / 128);
        gemm16<3072,1><<<grid, 256, GEMM_SMEM>>>((const __half*)pX,
                                                 (const __half*)pWq, b_qkv,
                                                 pQ, pK, pV);
    }
    // 2) Causal flash attention -> g_O16 [B,T,C]
    {
        dim3 grid(TT / 128, BB * HH);
        attn16<<<grid, 256, ATT_SMEM_BYTES>>>((__half*)pO);
    }
    // 3) Output projection -> d_out (fp32)
    {
        dim3 grid(1024 / 128, MM / 128);
        gemm16<1024,0><<<grid, 256, GEMM_SMEM>>>((const __half*)pO,
                                                 (const __half*)pWo, b_out,
                                                 out, nullptr, nullptr);
    }
}

// round 11
// speedup vs baseline: 9.6734x; 1.1140x over previous
#include <cuda_runtime.h>
#include <cuda_fp16.h>
#include <math.h>
#include <stdint.h>

// Problem constants
#define BB 4
#define TT 2048
#define CC 1024
#define HH 16
#define DHD 64
#define MM (BB*TT)          // 8192 rows

// Scratch (allocation-free rule: __device__ globals)
__device__ __half g_x16[MM*CC];          // x in fp16
__device__ __half g_Q16[BB*HH*TT*DHD];   // Q [B,H,T,Dh] fp16, pre-scaled by 1/8
__device__ __half g_K16[BB*HH*TT*DHD];
__device__ __half g_V16[BB*HH*TT*DHD];
__device__ __half g_O16[MM*CC];          // attention out [B,T,C] fp16
__device__ __half g_Wq16[3072*1024];     // W_qkv^T [N,K] fp16
__device__ __half g_Wo16[1024*1024];     // W_out^T [N,K] fp16

// ---------------------------------------------------------------------------
// helpers
// ---------------------------------------------------------------------------
__device__ __forceinline__ uint32_t smem_u32(const void* p) {
    uint32_t a;
    asm("{ .reg .u64 t; cvta.to.shared.u64 t, %1; cvt.u32.u64 %0, t; }"
        : "=r"(a) : "l"(p));
    return a;
}
__device__ __forceinline__ void cp16(uint32_t s, const void* g) {
    asm volatile("cp.async.cg.shared.global [%0], [%1], 16;" :: "r"(s), "l"(g));
}
#define CP_COMMIT() asm volatile("cp.async.commit_group;" ::: "memory")
#define CP_WAIT(n)  asm volatile("cp.async.wait_group %0;" :: "n"(n) : "memory")

__device__ __forceinline__ void mma_f16(float c[4], const unsigned a[4],
                                        const unsigned b0, const unsigned b1) {
    asm volatile(
        "mma.sync.aligned.m16n8k16.row.col.f32.f16.f16.f32 "
        "{%0,%1,%2,%3},{%4,%5,%6,%7},{%8,%9},{%0,%1,%2,%3};"
        : "+f"(c[0]), "+f"(c[1]), "+f"(c[2]), "+f"(c[3])
        : "r"(a[0]), "r"(a[1]), "r"(a[2]), "r"(a[3]), "r"(b0), "r"(b1));
}
__device__ __forceinline__ void ldsm4(unsigned r[4], uint32_t addr) {
    asm volatile("ldmatrix.sync.aligned.m8n8.x4.shared.b16 {%0,%1,%2,%3}, [%4];"
                 : "=r"(r[0]), "=r"(r[1]), "=r"(r[2]), "=r"(r[3]) : "r"(addr));
}
__device__ __forceinline__ void ldsm4t(unsigned r[4], uint32_t addr) {
    asm volatile("ldmatrix.sync.aligned.m8n8.x4.trans.shared.b16 {%0,%1,%2,%3}, [%4];"
                 : "=r"(r[0]), "=r"(r[1]), "=r"(r[2]), "=r"(r[3]) : "r"(addr));
}
__device__ __forceinline__ unsigned h2u(float a, float b) {
    __half2 h = __floats2half2_rn(a, b);
    return *(unsigned*)&h;
}

// ---------------------------------------------------------------------------
// Pre-pass kernels
// ---------------------------------------------------------------------------
__global__ __launch_bounds__(256)
void f2h_k(const float* __restrict__ src, __half* __restrict__ dst)
{
    int i = blockIdx.x * 256 + threadIdx.x;     // handles 8 floats
    float4 a = ((const float4*)src)[2 * i];
    float4 b = ((const float4*)src)[2 * i + 1];
    uint4 o;
    o.x = h2u(a.x, a.y); o.y = h2u(a.z, a.w);
    o.z = h2u(b.x, b.y); o.w = h2u(b.z, b.w);
    ((uint4*)dst)[i] = o;
}

// transpose + fp16: src[R][C] f32 -> dst[C][R] fp16
__global__ __launch_bounds__(256)
void transpose_h(const float* __restrict__ src, __half* __restrict__ dst,
                 int R, int C)
{
    __shared__ float tile[32][33];
    const int bx = blockIdx.x * 32;
    const int by = blockIdx.y * 32;
    const int tx = threadIdx.x & 31;
    const int ty = threadIdx.x >> 5;
#pragma unroll
    for (int i = 0; i < 32; i += 8)
        tile[ty + i][tx] = src[(size_t)(by + ty + i) * C + bx + tx];
    __syncthreads();
#pragma unroll
    for (int i = 0; i < 32; i += 8)
        dst[(size_t)(bx + ty + i) * R + by + tx] = __float2half(tile[tx][ty + i]);
}

// ---------------------------------------------------------------------------
// fp16 tensor-core GEMM: C[M,N] = A[M,1024] @ Bt[N,1024]^T + bias
// 128x128 tile, BK=32 fp16, 4-stage cp.async pipeline, ONE barrier per slab
// (issue into the slot freed by slab s-1, proven free by the barrier).
// ldmatrix.x4 fragment loads.  8 warps (2M x 4N), warp tile 64x32.
// MODE 0: fp32 store.  MODE 1: QKV scatter -> fp16 [B,H,T,Dh], Q scaled 1/8.
// ---------------------------------------------------------------------------
#define LSTR 20
#define TILE_WORDS (128*LSTR)
#define STG_WORDS (2*TILE_WORDS)
#define PIPE 4
#define GEMM_SMEM (PIPE*STG_WORDS*4)

template<int N, int MODE>
__global__ __launch_bounds__(256, 2)
void gemm16(const __half* __restrict__ A, const __half* __restrict__ Bt,
            const float* __restrict__ bias,
            void* __restrict__ O0, void* __restrict__ O1, void* __restrict__ O2)
{
    extern __shared__ uint32_t sw[];
    const int tid  = threadIdx.x;
    const int w    = tid >> 5;
    const int lane = tid & 31;
    const int g    = lane >> 2;
    const int t    = lane & 3;
    const int wm   = (w >> 2) * 64;
    const int wn   = (w & 3) * 32;
    const int bm   = blockIdx.y * 128;
    const int bn   = blockIdx.x * 128;
    const uint32_t smem_base = smem_u32(sw);

    const int l7        = lane & 7;
    const int a_row_off = l7 + ((lane & 8) ? 8 : 0);
    const int a_col4    = ((lane >> 4) & 1) * 4;
    const int sel       = lane >> 3;
    const int b_row_off = l7 + ((sel & 2) ? 8 : 0);
    const int b_col4    = (sel & 1) * 4;

    const int irow = tid >> 2;
    const int ic   = tid & 3;

    auto issue = [&](int slab, int st) {
        const int k0 = slab * 32;
        const uint32_t baseA = smem_base + (uint32_t)st * STG_WORDS * 4;
        const uint32_t baseB = baseA + TILE_WORDS * 4;
#pragma unroll
        for (int r = 0; r < 2; r++) {
            const int row = irow + r * 64;
            cp16(baseA + (row * LSTR + ic * 4) * 4,
                 &A[(size_t)(bm + row) * 1024 + k0 + ic * 8]);
            cp16(baseB + (row * LSTR + ic * 4) * 4,
                 &Bt[(size_t)(bn + row) * 1024 + k0 + ic * 8]);
        }
        CP_COMMIT();
    };

    issue(0, 0); issue(1, 1); issue(2, 2);   // PIPE-1 outstanding

    float acc[4][4][4];
#pragma unroll
    for (int mi = 0; mi < 4; mi++)
#pragma unroll
        for (int ni = 0; ni < 4; ni++)
#pragma unroll
            for (int c = 0; c < 4; c++) acc[mi][ni][c] = 0.f;

    for (int s = 0; s < 32; s++) {
        CP_WAIT(PIPE - 2);       // slab s resident
        __syncthreads();         // all warps done with slab s-1's slot
        if (s + PIPE - 1 < 32) issue(s + PIPE - 1, (s + PIPE - 1) % PIPE);
        const uint32_t As_b = smem_base + (uint32_t)(s % PIPE) * STG_WORDS * 4;
        const uint32_t Bs_b = As_b + TILE_WORDS * 4;
#pragma unroll
        for (int kk = 0; kk < 2; kk++) {
            unsigned a[4][4];
#pragma unroll
            for (int mi = 0; mi < 4; mi++)
                ldsm4(a[mi], As_b + (((wm + mi * 16) + a_row_off) * LSTR
                                     + a_col4 + kk * 8) * 4);
            unsigned b[2][4];
#pragma unroll
            for (int nip = 0; nip < 2; nip++)
                ldsm4(b[nip], Bs_b + (((wn + nip * 16) + b_row_off) * LSTR
                                      + b_col4 + kk * 8) * 4);
#pragma unroll
            for (int nip = 0; nip < 2; nip++)
#pragma unroll
                for (int mi = 0; mi < 4; mi++) {
                    mma_f16(acc[mi][2 * nip],     a[mi], b[nip][0], b[nip][1]);
                    mma_f16(acc[mi][2 * nip + 1], a[mi], b[nip][2], b[nip][3]);
                }
        }
    }

    // epilogue
#pragma unroll
    for (int mi = 0; mi < 4; mi++) {
#pragma unroll
        for (int ni = 0; ni < 4; ni++) {
            const int r0 = bm + wm + mi * 16 + g;
            const int c0 = bn + wn + ni * 8 + 2 * t;
            const float b0 = bias[c0], b1 = bias[c0 + 1];
            float v00 = acc[mi][ni][0] + b0, v01 = acc[mi][ni][1] + b1;
            float v10 = acc[mi][ni][2] + b0, v11 = acc[mi][ni][3] + b1;
            if (MODE == 0) {
                float* O = (float*)O0;
                *(float2*)&O[(size_t)r0 * N + c0]       = make_float2(v00, v01);
                *(float2*)&O[(size_t)(r0 + 8) * N + c0] = make_float2(v10, v11);
            } else {
                const int sec = c0 >> 10;          // 0=q,1=k,2=v
                const int cc  = c0 & 1023;
                const int h   = cc >> 6;
                const int d   = cc & 63;
                __half* dst = (sec == 0) ? (__half*)O0
                            : (sec == 1) ? (__half*)O1 : (__half*)O2;
                const float sc = (sec == 0) ? 0.125f : 1.0f;
                {
                    const int m = r0;
                    const size_t o = (((size_t)((m >> 11) * HH + h)) * TT + (m & 2047)) * DHD + d;
                    *(unsigned*)&dst[o] = h2u(v00 * sc, v01 * sc);
                }
                {
                    const int m = r0 + 8;
                    const size_t o = (((size_t)((m >> 11) * HH + h)) * TT + (m & 2047)) * DHD + d;
                    *(unsigned*)&dst[o] = h2u(v10 * sc, v11 * sc);
                }
            }
        }
    }
}

// ---------------------------------------------------------------------------
// Causal flash attention, fp16 mma m16n8k16.
// - K and V tiles streamed with cp.async, double-buffered (overlap with math)
// - V stored straight [key][d]; PV B-fragments via ldmatrix.x4.trans
// - P kept in registers (accumulator -> A-fragment identity)
// Block = 128 queries of one (b,h). 256 threads = 8 warps x 16 rows.
// ---------------------------------------------------------------------------
#define AST 36
#define KV_TILE_WORDS (64*AST)
#define ATT_WORDS (128*AST + 4*KV_TILE_WORDS)   // Q + 2 stages x (K,V)
#define ATT_SMEM_BYTES (ATT_WORDS * 4)

__global__ __launch_bounds__(256)
void attn16(__half* __restrict__ O)
{
    extern __shared__ uint32_t sm[];
    uint32_t* Qs = sm;                           // [128][36]

    const int tid  = threadIdx.x;
    const int w    = tid >> 5;
    const int lane = tid & 31;
    const int g    = lane >> 2;
    const int t    = lane & 3;
    const int bh   = blockIdx.y;                 // 0..63
    const int qt   = (gridDim.x - 1) - blockIdx.x;   // heavy tiles first
    const int b    = bh >> 4;
    const int h    = bh & 15;
    const size_t base = (size_t)bh * TT * DHD;
    const int q0   = qt * 128;
    const int rw   = w * 16;

    const uint32_t qs_byte  = smem_u32(sm);
    const uint32_t kv0_byte = qs_byte + 128 * AST * 4;   // stage0 K
    // layout per stage: K[64][36], V[64][36]

    const int l7        = lane & 7;
    const int a_row_off = l7 + ((lane & 8) ? 8 : 0);
    const int a_col4    = ((lane >> 4) & 1) * 4;
    const int sel       = lane >> 3;
    const int b_row_off = l7 + ((sel & 2) ? 8 : 0);
    const int b_col4    = (sel & 1) * 4;
    // trans-ldmatrix (V) lane addressing: m0:k0-7/d0, m1:k8-15/d0, m2:k0-7/d8, m3:k8-15/d8
    const int v_row_off = l7 + ((sel & 1) ? 8 : 0);
    const int v_col_b   = (sel >> 1) * 16;       // byte offset (8 halves)

    const int krow = tid >> 2;                   // 0..63
    const int kc0  = (tid & 3) * 2;              // chunk pair

    auto issue_kv = [&](int kt, int st) {
        const uint32_t kb = kv0_byte + (uint32_t)st * 2 * KV_TILE_WORDS * 4;
        const uint32_t vb = kb + KV_TILE_WORDS * 4;
        const size_t go = base + (size_t)(kt * 64 + krow) * DHD;
        cp16(kb + (krow * AST + kc0 * 4) * 4,       &g_K16[go + kc0 * 8]);
        cp16(kb + (krow * AST + (kc0 + 1) * 4) * 4, &g_K16[go + (kc0 + 1) * 8]);
        cp16(vb + (krow * AST + kc0 * 4) * 4,       &g_V16[go + kc0 * 8]);
        cp16(vb + (krow * AST + (kc0 + 1) * 4) * 4, &g_V16[go + (kc0 + 1) * 8]);
        CP_COMMIT();
    };

    issue_kv(0, 0);

    // Load Q tile (pre-scaled in GEMM epilogue): 128 rows x 8 uint4
#pragma unroll
    for (int it = 0; it < 4; it++) {
        const int i   = tid + it * 256;
        const int row = i >> 3;
        const int c   = i & 7;
        *(uint4*)&Qs[row * AST + c * 4] =
            *(const uint4*)&g_Q16[base + (size_t)(q0 + row) * DHD + c * 8];
    }

    float m0 = -INFINITY, m1 = -INFINITY, l0 = 0.f, l1 = 0.f;
    float oacc[8][4];
#pragma unroll
    for (int j = 0; j < 8; j++)
#pragma unroll
        for (int c = 0; c < 4; c++) oacc[j][c] = 0.f;

    const int ktmax = 2 * qt + 1;
    for (int kt = 0; kt <= ktmax; kt++) {
        const int k0g = kt * 64;
        CP_WAIT(0);              // tile kt resident
        __syncthreads();         // visible to all; prior stage free
        if (kt < ktmax) issue_kv(kt + 1, (kt + 1) & 1);

        const uint32_t ks_byte = kv0_byte + (uint32_t)(kt & 1) * 2 * KV_TILE_WORDS * 4;
        const uint32_t vs_byte = ks_byte + KV_TILE_WORDS * 4;

        // ---- S = Q K^T (warp rows rw..rw+15, 64 keys) ----
        float sacc[8][4];
#pragma unroll
        for (int j = 0; j < 8; j++)
#pragma unroll
            for (int c = 0; c < 4; c++) sacc[j][c] = 0.f;

#pragma unroll
        for (int kk = 0; kk < 4; kk++) {
            unsigned a[4];
            ldsm4(a, qs_byte + ((rw + a_row_off) * AST + a_col4 + kk * 8) * 4);
#pragma unroll
            for (int jp = 0; jp < 4; jp++) {
                unsigned bb[4];
                ldsm4(bb, ks_byte + ((jp * 16 + b_row_off) * AST
                                     + b_col4 + kk * 8) * 4);
                mma_f16(sacc[2 * jp],     a, bb[0], bb[1]);
                mma_f16(sacc[2 * jp + 1], a, bb[2], bb[3]);
            }
        }

        // ---- causal mask ----
        if (k0g + 63 > q0 + rw) {
            const int gr0 = q0 + rw + g, gr1 = gr0 + 8;
#pragma unroll
            for (int j = 0; j < 8; j++) {
                const int gc = k0g + j * 8 + 2 * t;
                if (gc     > gr0) sacc[j][0] = -INFINITY;
                if (gc + 1 > gr0) sacc[j][1] = -INFINITY;
                if (gc     > gr1) sacc[j][2] = -INFINITY;
                if (gc + 1 > gr1) sacc[j][3] = -INFINITY;
            }
        }

        // ---- online softmax (rows rw+g, rw+g+8) ----
        float mt0 = -INFINITY, mt1 = -INFINITY;
#pragma unroll
        for (int j = 0; j < 8; j++) {
            mt0 = fmaxf(mt0, fmaxf(sacc[j][0], sacc[j][1]));
            mt1 = fmaxf(mt1, fmaxf(sacc[j][2], sacc[j][3]));
        }
        mt0 = fmaxf(mt0, __shfl_xor_sync(0xffffffffu, mt0, 1));
        mt0 = fmaxf(mt0, __shfl_xor_sync(0xffffffffu, mt0, 2));
        mt1 = fmaxf(mt1, __shfl_xor_sync(0xffffffffu, mt1, 1));
        mt1 = fmaxf(mt1, __shfl_xor_sync(0xffffffffu, mt1, 2));

        const float mn0 = fmaxf(m0, mt0), mn1 = fmaxf(m1, mt1);
        const float cor0 = __expf(m0 - mn0), cor1 = __expf(m1 - mn1);

        float ls0 = 0.f, ls1 = 0.f;
#pragma unroll
        for (int j = 0; j < 8; j++) {
            sacc[j][0] = __expf(sacc[j][0] - mn0);
            sacc[j][1] = __expf(sacc[j][1] - mn0);
            sacc[j][2] = __expf(sacc[j][2] - mn1);
            sacc[j][3] = __expf(sacc[j][3] - mn1);
            ls0 += sacc[j][0] + sacc[j][1];
            ls1 += sacc[j][2] + sacc[j][3];
        }
        ls0 += __shfl_xor_sync(0xffffffffu, ls0, 1);
        ls0 += __shfl_xor_sync(0xffffffffu, ls0, 2);
        ls1 += __shfl_xor_sync(0xffffffffu, ls1, 1);
        ls1 += __shfl_xor_sync(0xffffffffu, ls1, 2);

        l0 = l0 * cor0 + ls0;  m0 = mn0;
        l1 = l1 * cor1 + ls1;  m1 = mn1;
#pragma unroll
        for (int j = 0; j < 8; j++) {
            oacc[j][0] *= cor0; oacc[j][1] *= cor0;
            oacc[j][2] *= cor1; oacc[j][3] *= cor1;
        }

        // ---- P accumulator -> A fragments (registers) ----
        unsigned pa[4][4];
#pragma unroll
        for (int kk = 0; kk < 4; kk++) {
            pa[kk][0] = h2u(sacc[2 * kk][0],     sacc[2 * kk][1]);
            pa[kk][1] = h2u(sacc[2 * kk][2],     sacc[2 * kk][3]);
            pa[kk][2] = h2u(sacc[2 * kk + 1][0], sacc[2 * kk + 1][1]);
            pa[kk][3] = h2u(sacc[2 * kk + 1][2], sacc[2 * kk + 1][3]);
        }

        // ---- O += P V ---- (B via ldmatrix.trans of V[key][d])
#pragma unroll
        for (int kk = 0; kk < 4; kk++) {
#pragma unroll
            for (int jp = 0; jp < 4; jp++) {
                unsigned bb[4];
                ldsm4t(bb, vs_byte + ((kk * 16 + v_row_off) * AST) * 4
                                   + jp * 32 + v_col_b);
                mma_f16(oacc[2 * jp],     pa[kk], bb[0], bb[1]);
                mma_f16(oacc[2 * jp + 1], pa[kk], bb[2], bb[3]);
            }
        }
    }

    // ---- normalize, write fp16 g_O [B,T,C] ----
    const float inv0 = 1.0f / l0, inv1 = 1.0f / l1;
    const int qrow = q0 + rw + g;
    const size_t ob0 = ((size_t)b * TT + qrow)     * CC + h * DHD;
    const size_t ob1 = ((size_t)b * TT + qrow + 8) * CC + h * DHD;
#pragma unroll
    for (int j = 0; j < 8; j++) {
        const int c = j * 8 + 2 * t;
        *(unsigned*)&O[ob0 + c] = h2u(oacc[j][0] * inv0, oacc[j][1] * inv0);
        *(unsigned*)&O[ob1 + c] = h2u(oacc[j][2] * inv1, oacc[j][3] * inv1);
    }
}

// ---------------------------------------------------------------------------
extern "C" void kernel_launch(void* const* d_in, const int* in_sizes, int n_in,
                              void* d_out, int out_size)
{
    const float* x     = (const float*)d_in[0];   // [4,2048,1024]
    const float* W_qkv = (const float*)d_in[1];   // [1024,3072]
    const float* b_qkv = (const float*)d_in[2];   // [3072]
    const float* W_out = (const float*)d_in[3];   // [1024,1024]
    const float* b_out = (const float*)d_in[4];   // [1024]
    float* out = (float*)d_out;                   // [4,2048,1024]

    void *pX, *pQ, *pK, *pV, *pO, *pWq, *pWo;
    cudaGetSymbolAddress(&pX,  g_x16);
    cudaGetSymbolAddress(&pQ,  g_Q16);
    cudaGetSymbolAddress(&pK,  g_K16);
    cudaGetSymbolAddress(&pV,  g_V16);
    cudaGetSymbolAddress(&pO,  g_O16);
    cudaGetSymbolAddress(&pWq, g_Wq16);
    cudaGetSymbolAddress(&pWo, g_Wo16);

    cudaFuncSetAttribute(attn16, cudaFuncAttributeMaxDynamicSharedMemorySize,
                         ATT_SMEM_BYTES);
    cudaFuncSetAttribute(gemm16<3072,1>,
                         cudaFuncAttributeMaxDynamicSharedMemorySize, GEMM_SMEM);
    cudaFuncSetAttribute(gemm16<1024,0>,
                         cudaFuncAttributeMaxDynamicSharedMemorySize, GEMM_SMEM);

    // 0) Pre-pass: x -> fp16, weights -> fp16 transposed [N,K]
    f2h_k<<<(MM * CC) / (256 * 8), 256>>>(x, (__half*)pX);
    transpose_h<<<dim3(3072/32, 1024/32), 256>>>(W_qkv, (__half*)pWq, 1024, 3072);
    transpose_h<<<dim3(1024/32, 1024/32), 256>>>(W_out, (__half*)pWo, 1024, 1024);

    // 1) QKV projection (fp16 mma + cp.async + ldmatrix)
    {
        dim3 grid(3072 / 128, MM / 128);
        gemm16<3072,1><<<grid, 256, GEMM_SMEM>>>((const __half*)pX,
                                                 (const __half*)pWq, b_qkv,
                                                 pQ, pK, pV);
    }
    // 2) Causal flash attention -> g_O16 [B,T,C]
    {
        dim3 grid(TT / 128, BB * HH);
        attn16<<<grid, 256, ATT_SMEM_BYTES>>>((__half*)pO);
    }
    // 3) Output projection -> d_out (fp32)
    {
        dim3 grid(1024 / 128, MM / 128);
        gemm16<1024,0><<<grid, 256, GEMM_SMEM>>>((const __half*)pO,
                                                 (const __half*)pWo, b_out,
                                                 out, nullptr, nullptr);
    }
}

// round 13
// speedup vs baseline: 10.5107x; 1.0866x over previous
#include <cuda_runtime.h>
#include <cuda_fp16.h>
#include <math.h>
#include <stdint.h>

// Problem constants
#define BB 4
#define TT 2048
#define CC 1024
#define HH 16
#define DHD 64
#define MM (BB*TT)          // 8192 rows

// Scratch (allocation-free rule: __device__ globals)
__device__ __half g_x16[MM*CC];          // x in fp16
__device__ __half g_Q16[BB*HH*TT*DHD];   // Q [B,H,T,Dh] fp16, scaled 0.125*log2(e)
__device__ __half g_K16[BB*HH*TT*DHD];
__device__ __half g_V16[BB*HH*TT*DHD];
__device__ __half g_O16[MM*CC];          // attention out [B,T,C] fp16
__device__ __half g_Wq16[3072*1024];     // W_qkv^T [N,K] fp16
__device__ __half g_Wo16[1024*1024];     // W_out^T [N,K] fp16

// ---------------------------------------------------------------------------
// helpers
// ---------------------------------------------------------------------------
__device__ __forceinline__ uint32_t smem_u32(const void* p) {
    uint32_t a;
    asm("{ .reg .u64 t; cvta.to.shared.u64 t, %1; cvt.u32.u64 %0, t; }"
        : "=r"(a) : "l"(p));
    return a;
}
__device__ __forceinline__ void cp16(uint32_t s, const void* g) {
    asm volatile("cp.async.cg.shared.global [%0], [%1], 16;" :: "r"(s), "l"(g));
}
#define CP_COMMIT() asm volatile("cp.async.commit_group;" ::: "memory")
#define CP_WAIT(n)  asm volatile("cp.async.wait_group %0;" :: "n"(n) : "memory")

__device__ __forceinline__ void mma_f16(float c[4], const unsigned a[4],
                                        const unsigned b0, const unsigned b1) {
    asm volatile(
        "mma.sync.aligned.m16n8k16.row.col.f32.f16.f16.f32 "
        "{%0,%1,%2,%3},{%4,%5,%6,%7},{%8,%9},{%0,%1,%2,%3};"
        : "+f"(c[0]), "+f"(c[1]), "+f"(c[2]), "+f"(c[3])
        : "r"(a[0]), "r"(a[1]), "r"(a[2]), "r"(a[3]), "r"(b0), "r"(b1));
}
__device__ __forceinline__ void ldsm4(unsigned r[4], uint32_t addr) {
    asm volatile("ldmatrix.sync.aligned.m8n8.x4.shared.b16 {%0,%1,%2,%3}, [%4];"
                 : "=r"(r[0]), "=r"(r[1]), "=r"(r[2]), "=r"(r[3]) : "r"(addr));
}
__device__ __forceinline__ void ldsm4t(unsigned r[4], uint32_t addr) {
    asm volatile("ldmatrix.sync.aligned.m8n8.x4.trans.shared.b16 {%0,%1,%2,%3}, [%4];"
                 : "=r"(r[0]), "=r"(r[1]), "=r"(r[2]), "=r"(r[3]) : "r"(addr));
}
__device__ __forceinline__ unsigned h2u(float a, float b) {
    __half2 h = __floats2half2_rn(a, b);
    return *(unsigned*)&h;
}
__device__ __forceinline__ unsigned ex2h2(unsigned x) {
    unsigned r;
    asm("ex2.approx.f16x2 %0, %1;" : "=r"(r) : "r"(x));
    return r;
}

// ---------------------------------------------------------------------------
// Pre-pass kernels
// ---------------------------------------------------------------------------
__global__ __launch_bounds__(256)
void f2h_k(const float* __restrict__ src, __half* __restrict__ dst)
{
    int i = blockIdx.x * 256 + threadIdx.x;     // handles 8 floats
    float4 a = ((const float4*)src)[2 * i];
    float4 b = ((const float4*)src)[2 * i + 1];
    uint4 o;
    o.x = h2u(a.x, a.y); o.y = h2u(a.z, a.w);
    o.z = h2u(b.x, b.y); o.w = h2u(b.z, b.w);
    ((uint4*)dst)[i] = o;
}

// transpose + fp16: src[R][C] f32 -> dst[C][R] fp16
__global__ __launch_bounds__(256)
void transpose_h(const float* __restrict__ src, __half* __restrict__ dst,
                 int R, int C)
{
    __shared__ float tile[32][33];
    const int bx = blockIdx.x * 32;
    const int by = blockIdx.y * 32;
    const int tx = threadIdx.x & 31;
    const int ty = threadIdx.x >> 5;
#pragma unroll
    for (int i = 0; i < 32; i += 8)
        tile[ty + i][tx] = src[(size_t)(by + ty + i) * C + bx + tx];
    __syncthreads();
#pragma unroll
    for (int i = 0; i < 32; i += 8)
        dst[(size_t)(bx + ty + i) * R + by + tx] = __float2half(tile[tx][ty + i]);
}

// ---------------------------------------------------------------------------
// fp16 tensor-core GEMM: C[M,N] = A[M,1024] @ Bt[N,1024]^T + bias
// 128x128 tile, BK=64 fp16 (4 x k16) per stage, 3-stage cp.async pipeline,
// ONE barrier per 64-K slab.  ldmatrix.x4 fragment loads.
// 8 warps (2M x 4N), warp tile 64x32.
// MODE 0: fp32 store.  MODE 1: QKV scatter -> fp16 [B,H,T,Dh],
//         Q scaled by 0.125*log2(e) (exp2-domain softmax downstream).
// ---------------------------------------------------------------------------
#define LSTR 36                      // words per row: 32 data + 4 pad
#define TILE_WORDS (128*LSTR)        // 4608
#define STG_WORDS (2*TILE_WORDS)
#define PIPE 3
#define NSLAB 16                     // 1024 / 64
#define GEMM_SMEM (PIPE*STG_WORDS*4) // 110592 B

#define QSCALE 0.18033688f           // 0.125 * log2(e)

template<int N, int MODE>
__global__ __launch_bounds__(256, 2)
void gemm16(const __half* __restrict__ A, const __half* __restrict__ Bt,
            const float* __restrict__ bias,
            void* __restrict__ O0, void* __restrict__ O1, void* __restrict__ O2)
{
    extern __shared__ uint32_t sw[];
    const int tid  = threadIdx.x;
    const int w    = tid >> 5;
    const int lane = tid & 31;
    const int g    = lane >> 2;
    const int t    = lane & 3;
    const int wm   = (w >> 2) * 64;
    const int wn   = (w & 3) * 32;
    const int bm   = blockIdx.y * 128;
    const int bn   = blockIdx.x * 128;
    const uint32_t smem_base = smem_u32(sw);

    const int l7        = lane & 7;
    const int a_row_off = l7 + ((lane & 8) ? 8 : 0);
    const int a_col4    = ((lane >> 4) & 1) * 4;
    const int sel       = lane >> 3;
    const int b_row_off = l7 + ((sel & 2) ? 8 : 0);
    const int b_col4    = (sel & 1) * 4;

    auto issue = [&](int slab, int st) {
        const int k0 = slab * 64;
        const uint32_t baseA = smem_base + (uint32_t)st * STG_WORDS * 4;
        const uint32_t baseB = baseA + TILE_WORDS * 4;
#pragma unroll
        for (int r = 0; r < 4; r++) {
            const int i   = tid + r * 256;     // chunk index, 1024 per tile
            const int row = i >> 3;
            const int c   = i & 7;
            cp16(baseA + (row * LSTR + c * 4) * 4,
                 &A[(size_t)(bm + row) * 1024 + k0 + c * 8]);
            cp16(baseB + (row * LSTR + c * 4) * 4,
                 &Bt[(size_t)(bn + row) * 1024 + k0 + c * 8]);
        }
        CP_COMMIT();
    };

    issue(0, 0); issue(1, 1);        // PIPE-1 outstanding

    float acc[4][4][4];
#pragma unroll
    for (int mi = 0; mi < 4; mi++)
#pragma unroll
        for (int ni = 0; ni < 4; ni++)
#pragma unroll
            for (int c = 0; c < 4; c++) acc[mi][ni][c] = 0.f;

    for (int s = 0; s < NSLAB; s++) {
        CP_WAIT(PIPE - 2);           // slab s resident
        __syncthreads();             // all warps done with slab s-1's slot
        if (s + PIPE - 1 < NSLAB) issue(s + PIPE - 1, (s + PIPE - 1) % PIPE);
        const uint32_t As_b = smem_base + (uint32_t)(s % PIPE) * STG_WORDS * 4;
        const uint32_t Bs_b = As_b + TILE_WORDS * 4;
#pragma unroll
        for (int kk = 0; kk < 4; kk++) {
            unsigned a[4][4];
#pragma unroll
            for (int mi = 0; mi < 4; mi++)
                ldsm4(a[mi], As_b + (((wm + mi * 16) + a_row_off) * LSTR
                                     + a_col4 + kk * 8) * 4);
            unsigned b[2][4];
#pragma unroll
            for (int nip = 0; nip < 2; nip++)
                ldsm4(b[nip], Bs_b + (((wn + nip * 16) + b_row_off) * LSTR
                                      + b_col4 + kk * 8) * 4);
#pragma unroll
            for (int nip = 0; nip < 2; nip++)
#pragma unroll
                for (int mi = 0; mi < 4; mi++) {
                    mma_f16(acc[mi][2 * nip],     a[mi], b[nip][0], b[nip][1]);
                    mma_f16(acc[mi][2 * nip + 1], a[mi], b[nip][2], b[nip][3]);
                }
        }
    }

    // epilogue
#pragma unroll
    for (int mi = 0; mi < 4; mi++) {
#pragma unroll
        for (int ni = 0; ni < 4; ni++) {
            const int r0 = bm + wm + mi * 16 + g;
            const int c0 = bn + wn + ni * 8 + 2 * t;
            const float b0 = bias[c0], b1 = bias[c0 + 1];
            float v00 = acc[mi][ni][0] + b0, v01 = acc[mi][ni][1] + b1;
            float v10 = acc[mi][ni][2] + b0, v11 = acc[mi][ni][3] + b1;
            if (MODE == 0) {
                float* O = (float*)O0;
                *(float2*)&O[(size_t)r0 * N + c0]       = make_float2(v00, v01);
                *(float2*)&O[(size_t)(r0 + 8) * N + c0] = make_float2(v10, v11);
            } else {
                const int sec = c0 >> 10;          // 0=q,1=k,2=v
                const int cc  = c0 & 1023;
                const int h   = cc >> 6;
                const int d   = cc & 63;
                __half* dst = (sec == 0) ? (__half*)O0
                            : (sec == 1) ? (__half*)O1 : (__half*)O2;
                const float sc = (sec == 0) ? QSCALE : 1.0f;
                {
                    const int m = r0;
                    const size_t o = (((size_t)((m >> 11) * HH + h)) * TT + (m & 2047)) * DHD + d;
                    *(unsigned*)&dst[o] = h2u(v00 * sc, v01 * sc);
                }
                {
                    const int m = r0 + 8;
                    const size_t o = (((size_t)((m >> 11) * HH + h)) * TT + (m & 2047)) * DHD + d;
                    *(unsigned*)&dst[o] = h2u(v10 * sc, v11 * sc);
                }
            }
        }
    }
}

// ---------------------------------------------------------------------------
// Causal flash attention, fp16 mma m16n8k16, exp2-domain softmax with
// ex2.approx.f16x2 (p computed directly as fp16 pairs = PV A-fragments).
// K/V double-buffered via cp.async; V via ldmatrix.x4.trans.
// Block = 128 queries of one (b,h). 256 threads = 8 warps x 16 rows.
// ---------------------------------------------------------------------------
#define AST 36
#define KV_TILE_WORDS (64*AST)
#define ATT_WORDS (128*AST + 4*KV_TILE_WORDS)   // Q + 2 stages x (K,V)
#define ATT_SMEM_BYTES (ATT_WORDS * 4)

__global__ __launch_bounds__(256)
void attn16(__half* __restrict__ O)
{
    extern __shared__ uint32_t sm[];
    uint32_t* Qs = sm;                           // [128][36]

    const int tid  = threadIdx.x;
    const int w    = tid >> 5;
    const int lane = tid & 31;
    const int g    = lane >> 2;
    const int t    = lane & 3;
    const int bh   = blockIdx.y;                 // 0..63
    const int qt   = (gridDim.x - 1) - blockIdx.x;   // heavy tiles first
    const int b    = bh >> 4;
    const int h    = bh & 15;
    const size_t base = (size_t)bh * TT * DHD;
    const int q0   = qt * 128;
    const int rw   = w * 16;

    const uint32_t qs_byte  = smem_u32(sm);
    const uint32_t kv0_byte = qs_byte + 128 * AST * 4;   // stage0 K

    const int l7        = lane & 7;
    const int a_row_off = l7 + ((lane & 8) ? 8 : 0);
    const int a_col4    = ((lane >> 4) & 1) * 4;
    const int sel       = lane >> 3;
    const int b_row_off = l7 + ((sel & 2) ? 8 : 0);
    const int b_col4    = (sel & 1) * 4;
    const int v_row_off = l7 + ((sel & 1) ? 8 : 0);
    const int v_col_b   = (sel >> 1) * 16;

    const int krow = tid >> 2;                   // 0..63
    const int kc0  = (tid & 3) * 2;

    auto issue_kv = [&](int kt, int st) {
        const uint32_t kb = kv0_byte + (uint32_t)st * 2 * KV_TILE_WORDS * 4;
        const uint32_t vb = kb + KV_TILE_WORDS * 4;
        const size_t go = base + (size_t)(kt * 64 + krow) * DHD;
        cp16(kb + (krow * AST + kc0 * 4) * 4,       &g_K16[go + kc0 * 8]);
        cp16(kb + (krow * AST + (kc0 + 1) * 4) * 4, &g_K16[go + (kc0 + 1) * 8]);
        cp16(vb + (krow * AST + kc0 * 4) * 4,       &g_V16[go + kc0 * 8]);
        cp16(vb + (krow * AST + (kc0 + 1) * 4) * 4, &g_V16[go + (kc0 + 1) * 8]);
        CP_COMMIT();
    };

    issue_kv(0, 0);

    // Load Q tile (scaled by 0.125*log2e in GEMM epilogue)
#pragma unroll
    for (int it = 0; it < 4; it++) {
        const int i   = tid + it * 256;
        const int row = i >> 3;
        const int c   = i & 7;
        *(uint4*)&Qs[row * AST + c * 4] =
            *(const uint4*)&g_Q16[base + (size_t)(q0 + row) * DHD + c * 8];
    }

    float m0 = -INFINITY, m1 = -INFINITY, l0 = 0.f, l1 = 0.f;
    float oacc[8][4];
#pragma unroll
    for (int j = 0; j < 8; j++)
#pragma unroll
        for (int c = 0; c < 4; c++) oacc[j][c] = 0.f;

    const int ktmax = 2 * qt + 1;
    for (int kt = 0; kt <= ktmax; kt++) {
        const int k0g = kt * 64;
        CP_WAIT(0);
        __syncthreads();
        if (kt < ktmax) issue_kv(kt + 1, (kt + 1) & 1);

        const uint32_t ks_byte = kv0_byte + (uint32_t)(kt & 1) * 2 * KV_TILE_WORDS * 4;
        const uint32_t vs_byte = ks_byte + KV_TILE_WORDS * 4;

        // ---- S = Q K^T (log2-domain; Q pre-scaled) ----
        float sacc[8][4];
#pragma unroll
        for (int j = 0; j < 8; j++)
#pragma unroll
            for (int c = 0; c < 4; c++) sacc[j][c] = 0.f;

#pragma unroll
        for (int kk = 0; kk < 4; kk++) {
            unsigned a[4];
            ldsm4(a, qs_byte + ((rw + a_row_off) * AST + a_col4 + kk * 8) * 4);
#pragma unroll
            for (int jp = 0; jp < 4; jp++) {
                unsigned bb[4];
                ldsm4(bb, ks_byte + ((jp * 16 + b_row_off) * AST
                                     + b_col4 + kk * 8) * 4);
                mma_f16(sacc[2 * jp],     a, bb[0], bb[1]);
                mma_f16(sacc[2 * jp + 1], a, bb[2], bb[3]);
            }
        }

        // ---- causal mask ----
        if (k0g + 63 > q0 + rw) {
            const int gr0 = q0 + rw + g, gr1 = gr0 + 8;
#pragma unroll
            for (int j = 0; j < 8; j++) {
                const int gc = k0g + j * 8 + 2 * t;
                if (gc     > gr0) sacc[j][0] = -INFINITY;
                if (gc + 1 > gr0) sacc[j][1] = -INFINITY;
                if (gc     > gr1) sacc[j][2] = -INFINITY;
                if (gc + 1 > gr1) sacc[j][3] = -INFINITY;
            }
        }

        // ---- online softmax (exp2 domain; rows rw+g, rw+g+8) ----
        float mt0 = -INFINITY, mt1 = -INFINITY;
#pragma unroll
        for (int j = 0; j < 8; j++) {
            mt0 = fmaxf(mt0, fmaxf(sacc[j][0], sacc[j][1]));
            mt1 = fmaxf(mt1, fmaxf(sacc[j][2], sacc[j][3]));
        }
        mt0 = fmaxf(mt0, __shfl_xor_sync(0xffffffffu, mt0, 1));
        mt0 = fmaxf(mt0, __shfl_xor_sync(0xffffffffu, mt0, 2));
        mt1 = fmaxf(mt1, __shfl_xor_sync(0xffffffffu, mt1, 1));
        mt1 = fmaxf(mt1, __shfl_xor_sync(0xffffffffu, mt1, 2));

        const float mn0 = fmaxf(m0, mt0), mn1 = fmaxf(m1, mt1);
        const float cor0 = exp2f(m0 - mn0), cor1 = exp2f(m1 - mn1);

        // p = 2^(s - m), computed as fp16 pairs -> directly the PV A-fragments
        unsigned pa[4][4];
        float ls0 = 0.f, ls1 = 0.f;
#pragma unroll
        for (int j = 0; j < 8; j++) {
            const unsigned p01 = ex2h2(h2u(sacc[j][0] - mn0, sacc[j][1] - mn0));
            const unsigned p23 = ex2h2(h2u(sacc[j][2] - mn1, sacc[j][3] - mn1));
            const float2 f01 = __half22float2(*(const __half2*)&p01);
            const float2 f23 = __half22float2(*(const __half2*)&p23);
            ls0 += f01.x + f01.y;
            ls1 += f23.x + f23.y;
            pa[j >> 1][(j & 1) * 2 + 0] = p01;
            pa[j >> 1][(j & 1) * 2 + 1] = p23;
        }
        ls0 += __shfl_xor_sync(0xffffffffu, ls0, 1);
        ls0 += __shfl_xor_sync(0xffffffffu, ls0, 2);
        ls1 += __shfl_xor_sync(0xffffffffu, ls1, 1);
        ls1 += __shfl_xor_sync(0xffffffffu, ls1, 2);

        l0 = l0 * cor0 + ls0;  m0 = mn0;
        l1 = l1 * cor1 + ls1;  m1 = mn1;
#pragma unroll
        for (int j = 0; j < 8; j++) {
            oacc[j][0] *= cor0; oacc[j][1] *= cor0;
            oacc[j][2] *= cor1; oacc[j][3] *= cor1;
        }

        // ---- O += P V ---- (B via ldmatrix.trans of V[key][d])
#pragma unroll
        for (int kk = 0; kk < 4; kk++) {
#pragma unroll
            for (int jp = 0; jp < 4; jp++) {
                unsigned bb[4];
                ldsm4t(bb, vs_byte + ((kk * 16 + v_row_off) * AST) * 4
                                   + jp * 32 + v_col_b);
                mma_f16(oacc[2 * jp],     pa[kk], bb[0], bb[1]);
                mma_f16(oacc[2 * jp + 1], pa[kk], bb[2], bb[3]);
            }
        }
    }

    // ---- normalize, write fp16 g_O [B,T,C] ----
    const float inv0 = 1.0f / l0, inv1 = 1.0f / l1;
    const int qrow = q0 + rw + g;
    const size_t ob0 = ((size_t)b * TT + qrow)     * CC + h * DHD;
    const size_t ob1 = ((size_t)b * TT + qrow + 8) * CC + h * DHD;
#pragma unroll
    for (int j = 0; j < 8; j++) {
        const int c = j * 8 + 2 * t;
        *(unsigned*)&O[ob0 + c] = h2u(oacc[j][0] * inv0, oacc[j][1] * inv0);
        *(unsigned*)&O[ob1 + c] = h2u(oacc[j][2] * inv1, oacc[j][3] * inv1);
    }
}

// ---------------------------------------------------------------------------
extern "C" void kernel_launch(void* const* d_in, const int* in_sizes, int n_in,
                              void* d_out, int out_size)
{
    const float* x     = (const float*)d_in[0];   // [4,2048,1024]
    const float* W_qkv = (const float*)d_in[1];   // [1024,3072]
    const float* b_qkv = (const float*)d_in[2];   // [3072]
    const float* W_out = (const float*)d_in[3];   // [1024,1024]
    const float* b_out = (const float*)d_in[4];   // [1024]
    float* out = (float*)d_out;                   // [4,2048,1024]

    void *pX, *pQ, *pK, *pV, *pO, *pWq, *pWo;
    cudaGetSymbolAddress(&pX,  g_x16);
    cudaGetSymbolAddress(&pQ,  g_Q16);
    cudaGetSymbolAddress(&pK,  g_K16);
    cudaGetSymbolAddress(&pV,  g_V16);
    cudaGetSymbolAddress(&pO,  g_O16);
    cudaGetSymbolAddress(&pWq, g_Wq16);
    cudaGetSymbolAddress(&pWo, g_Wo16);

    cudaFuncSetAttribute(attn16, cudaFuncAttributeMaxDynamicSharedMemorySize,
                         ATT_SMEM_BYTES);
    cudaFuncSetAttribute(gemm16<3072,1>,
                         cudaFuncAttributeMaxDynamicSharedMemorySize, GEMM_SMEM);
    cudaFuncSetAttribute(gemm16<1024,0>,
                         cudaFuncAttributeMaxDynamicSharedMemorySize, GEMM_SMEM);

    // 0) Pre-pass: x -> fp16, weights -> fp16 transposed [N,K]
    f2h_k<<<(MM * CC) / (256 * 8), 256>>>(x, (__half*)pX);
    transpose_h<<<dim3(3072/32, 1024/32), 256>>>(W_qkv, (__half*)pWq, 1024, 3072);
    transpose_h<<<dim3(1024/32, 1024/32), 256>>>(W_out, (__half*)pWo, 1024, 1024);

    // 1) QKV projection (fp16 mma + cp.async + ldmatrix, BK=64 pipeline)
    {
        dim3 grid(3072 / 128, MM / 128);
        gemm16<3072,1><<<grid, 256, GEMM_SMEM>>>((const __half*)pX,
                                                 (const __half*)pWq, b_qkv,
                                                 pQ, pK, pV);
    }
    // 2) Causal flash attention -> g_O16 [B,T,C]
    {
        dim3 grid(TT / 128, BB * HH);
        attn16<<<grid, 256, ATT_SMEM_BYTES>>>((__half*)pO);
    }
    // 3) Output projection -> d_out (fp32)
    {
        dim3 grid(1024 / 128, MM / 128);
        gemm16<1024,0><<<grid, 256, GEMM_SMEM>>>((const __half*)pO,
                                                 (const __half*)pWo, b_out,
                                                 out, nullptr, nullptr);
    }
}